// round 7
// baseline (speedup 1.0000x reference)
#include <cuda_runtime.h>
#include <cuda_bf16.h>
#include <math.h>
#include <stdint.h>

// Problem constants
#define BATCH 2
#define SEQ   2048
#define DM    1024
#define NH    16
#define DK    64
#define MTOT  (BATCH*SEQ)       // 4096

// ---------------- scratch (no allocations allowed) ----------------
__device__ float g_Qh [BATCH*NH*SEQ*DK];   // [b*h][s][dk], pre-scaled by 1/8
__device__ float g_KhT[BATCH*NH*DK*SEQ];   // [b*h][dk][s]  (transposed K heads)
__device__ float g_Vh [BATCH*NH*SEQ*DK];   // [b*h][s][dk]
__device__ float g_At [MTOT*DM];           // attention output, [b*s][h*dk]

// ==================== HMMA bf16 3-pass GEMM ====================
// Y(MxN) = X(MxK) @ W(KxN) (+bias), M=4096, N=K=1024.
// CTA tile 128x128, 8 warps in 2(M)x4(N), warp tile 64x32.
// K streamed in blocks of 64, double-buffered SMEM.
// 3-pass split: X=Xhi+Xlo, W=Whi+Wlo; D += Xhi*Whi + Xhi*Wlo + Xlo*Whi.
// modes: 0 plain, 1 Q(head,+bias,*0.125), 2 K^T(head,no bias), 3 V(head,+bias)

#define KBLK  64
#define ASTR  72                      // halves per row (A: [m][k], B: [n][k])
#define TILE_BYTES (128 * ASTR * 2)   // 18432
#define OFF_A_HI 0
#define OFF_A_LO (TILE_BYTES)
#define OFF_B_HI (2 * TILE_BYTES)
#define OFF_B_LO (3 * TILE_BYTES)
#define GBUFSZ   (4 * TILE_BYTES)     // 73728 per buffer
#define SMEM_GEMM (2 * GBUFSZ)        // 147456

__device__ __forceinline__ void split2(float a, float b, uint32_t& hi, uint32_t& lo) {
    __nv_bfloat162 h = __float22bfloat162_rn(make_float2(a, b));
    float2 hf = __bfloat1622float2(h);
    __nv_bfloat162 l = __float22bfloat162_rn(make_float2(a - hf.x, b - hf.y));
    hi = *(uint32_t*)&h;
    lo = *(uint32_t*)&l;
}

__device__ __forceinline__ void mma16816(float* c, const uint32_t* a, const uint32_t* b) {
    asm volatile(
        "mma.sync.aligned.m16n8k16.row.col.f32.bf16.bf16.f32 "
        "{%0,%1,%2,%3},{%4,%5,%6,%7},{%8,%9},{%0,%1,%2,%3};"
        : "+f"(c[0]), "+f"(c[1]), "+f"(c[2]), "+f"(c[3])
        : "r"(a[0]), "r"(a[1]), "r"(a[2]), "r"(a[3]), "r"(b[0]), "r"(b[1]));
}

// stage one K-block (64 wide) into SMEM buffer `buf` as hi/lo bf16
__device__ __forceinline__ void stage_blk(const float* __restrict__ X,
                                          const float* __restrict__ W,
                                          char* sm, int buf, int blk,
                                          int bm, int bn, int tid)
{
    char* base = sm + buf * GBUFSZ;
    const int k0 = blk * KBLK;

    // ---- A: 128(m) x 64(k), row-major [m][k], stride ASTR halves ----
    {
        const int m  = tid >> 1;
        const int kh = (tid & 1) * 32;
        const float4* src = (const float4*)(X + (size_t)(bm + m) * DM + k0 + kh);
        __nv_bfloat16* ah = (__nv_bfloat16*)(base + OFF_A_HI) + m * ASTR + kh;
        __nv_bfloat16* al = (__nv_bfloat16*)(base + OFF_A_LO) + m * ASTR + kh;
#pragma unroll
        for (int i = 0; i < 8; i++) {
            float4 x = src[i];
            uint32_t h0, l0, h1, l1;
            split2(x.x, x.y, h0, l0);
            split2(x.z, x.w, h1, l1);
            *(uint2*)(ah + 4 * i) = make_uint2(h0, h1);
            *(uint2*)(al + 4 * i) = make_uint2(l0, l1);
        }
    }
    // ---- B: stored TRANSPOSED [n][k], stride ASTR halves ----
    // warp w: n = (w&3)*32 + lane, k range (w>>2)*32 .. +32
    {
        const int w    = tid >> 5;
        const int lane = tid & 31;
        const int n    = (w & 3) * 32 + lane;
        const int kh   = (w >> 2) * 32;
        const float* src = W + (size_t)(k0 + kh) * DM + bn + n;
        __nv_bfloat16* bh = (__nv_bfloat16*)(base + OFF_B_HI) + n * ASTR + kh;
        __nv_bfloat16* bl = (__nv_bfloat16*)(base + OFF_B_LO) + n * ASTR + kh;
#pragma unroll
        for (int kk = 0; kk < 32; kk += 2) {
            float x0 = src[(size_t)kk * DM];
            float x1 = src[(size_t)(kk + 1) * DM];
            uint32_t h, l;
            split2(x0, x1, h, l);
            *(uint32_t*)(bh + kk) = h;
            *(uint32_t*)(bl + kk) = l;
        }
    }
}

__device__ __forceinline__ void store1(float* __restrict__ Y,
                                       const float* __restrict__ bias,
                                       int mode, int m, int n, float v)
{
    if (bias) v += bias[n];
    if (mode == 1) v *= 0.125f;
    size_t idx;
    if (mode == 0) {
        idx = (size_t)m * DM + n;
    } else {
        int bq = m >> 11, sq = m & (SEQ - 1);
        int h  = n >> 6,  dk = n & (DK - 1);
        if (mode == 2) idx = (size_t)((bq * NH + h) * DK + dk) * SEQ + sq;
        else           idx = (size_t)((bq * NH + h) * SEQ + sq) * DK + dk;
    }
    Y[idx] = v;
}

__global__ __launch_bounds__(256, 1)
void tc_gemm(const float* __restrict__ X, const float* __restrict__ W,
             const float* __restrict__ bias, float* __restrict__ Y, int mode)
{
    extern __shared__ char sm[];
    const int tid  = threadIdx.x;
    const int wid  = tid >> 5;
    const int lane = tid & 31;
    const int wm   = wid >> 2;       // 0..1
    const int wn   = wid & 3;        // 0..3
    const int bm   = blockIdx.y * 128;
    const int bn   = blockIdx.x * 128;

    float acc[4][4][4];
#pragma unroll
    for (int i = 0; i < 4; i++)
#pragma unroll
        for (int j = 0; j < 4; j++)
#pragma unroll
            for (int r = 0; r < 4; r++) acc[i][j][r] = 0.f;

    stage_blk(X, W, sm, 0, 0, bm, bn, tid);
    __syncthreads();

    const int r4 = lane >> 2;        // 0..7
    const int c4 = (lane & 3) * 2;   // 0,2,4,6

    for (int blk = 0; blk < DM / KBLK; blk++) {
        const int cur = blk & 1;
        if (blk + 1 < DM / KBLK)
            stage_blk(X, W, sm, cur ^ 1, blk + 1, bm, bn, tid);

        const char* base = sm + cur * GBUFSZ;
        const __nv_bfloat16* Ah = (const __nv_bfloat16*)(base + OFF_A_HI);
        const __nv_bfloat16* Al = (const __nv_bfloat16*)(base + OFF_A_LO);
        const __nv_bfloat16* Bh = (const __nv_bfloat16*)(base + OFF_B_HI);
        const __nv_bfloat16* Bl = (const __nv_bfloat16*)(base + OFF_B_LO);

#pragma unroll
        for (int ks = 0; ks < 4; ks++) {
            const int kc = ks * 16;
            uint32_t ah[4][4], al[4][4], bh[4][2], bl[4][2];
#pragma unroll
            for (int mt = 0; mt < 4; mt++) {
                const int m0 = wm * 64 + mt * 16;
                const int o00 = (m0 + r4)     * ASTR + kc + c4;
                const int o10 = (m0 + r4 + 8) * ASTR + kc + c4;
                ah[mt][0] = *(const uint32_t*)(Ah + o00);
                ah[mt][1] = *(const uint32_t*)(Ah + o10);
                ah[mt][2] = *(const uint32_t*)(Ah + o00 + 8);
                ah[mt][3] = *(const uint32_t*)(Ah + o10 + 8);
                al[mt][0] = *(const uint32_t*)(Al + o00);
                al[mt][1] = *(const uint32_t*)(Al + o10);
                al[mt][2] = *(const uint32_t*)(Al + o00 + 8);
                al[mt][3] = *(const uint32_t*)(Al + o10 + 8);
            }
#pragma unroll
            for (int nt = 0; nt < 4; nt++) {
                const int n0 = wn * 32 + nt * 8 + r4;
                const int ob = n0 * ASTR + kc + c4;
                bh[nt][0] = *(const uint32_t*)(Bh + ob);
                bh[nt][1] = *(const uint32_t*)(Bh + ob + 8);
                bl[nt][0] = *(const uint32_t*)(Bl + ob);
                bl[nt][1] = *(const uint32_t*)(Bl + ob + 8);
            }
            // 3-pass: hi*hi, hi*lo, lo*hi
#pragma unroll
            for (int mt = 0; mt < 4; mt++)
#pragma unroll
                for (int nt = 0; nt < 4; nt++)
                    mma16816(acc[mt][nt], ah[mt], bh[nt]);
#pragma unroll
            for (int mt = 0; mt < 4; mt++)
#pragma unroll
                for (int nt = 0; nt < 4; nt++)
                    mma16816(acc[mt][nt], ah[mt], bl[nt]);
#pragma unroll
            for (int mt = 0; mt < 4; mt++)
#pragma unroll
                for (int nt = 0; nt < 4; nt++)
                    mma16816(acc[mt][nt], al[mt], bh[nt]);
        }
        __syncthreads();
    }

    // ---------------- epilogue ----------------
#pragma unroll
    for (int mt = 0; mt < 4; mt++) {
        const int m0 = bm + wm * 64 + mt * 16 + r4;
#pragma unroll
        for (int nt = 0; nt < 4; nt++) {
            const int n0 = bn + wn * 32 + nt * 8 + c4;
            store1(Y, bias, mode, m0,     n0,     acc[mt][nt][0]);
            store1(Y, bias, mode, m0,     n0 + 1, acc[mt][nt][1]);
            store1(Y, bias, mode, m0 + 8, n0,     acc[mt][nt][2]);
            store1(Y, bias, mode, m0 + 8, n0 + 1, acc[mt][nt][3]);
        }
    }
}

// ---------------- flash attention (fp32, online softmax) ----------------
#define PSTR 68

__global__ __launch_bounds__(256)
void attn_kernel(const float* __restrict__ Qh, const float* __restrict__ KhT,
                 const float* __restrict__ Vh, const int* __restrict__ mask,
                 float* __restrict__ Out)
{
    extern __shared__ float smf[];
    float* Qs = smf;                  // [64][64]
    float* Ks = smf + 64 * 64;        // K^T tile [64 d][64 c]
    float* Vs = smf + 2 * 64 * 64;    // [64 j][64 d]
    float* Ps = smf + 3 * 64 * 64;    // [64][PSTR]

    const int tid = threadIdx.x;
    const int tx  = tid & 15;
    const int ty  = tid >> 4;
    const int qt  = blockIdx.x;
    const int bh  = blockIdx.y;
    const int b   = bh >> 4;

    const float* Qbase = Qh  + (bh * SEQ + qt * 64) * DK;
    const float* Kbase = KhT + bh * DK * SEQ;
    const float* Vbase = Vh  + bh * SEQ * DK;
    const int*   Mbase = mask + (b * SEQ + qt * 64) * SEQ;

#pragma unroll
    for (int r = 0; r < 4; r++) {
        int s = tid + r * 256;
        ((float4*)Qs)[s] = ((const float4*)Qbase)[s];
    }

    float m_run[4], l_run[4], o[4][4];
#pragma unroll
    for (int i = 0; i < 4; i++) {
        m_run[i] = -1e38f;
        l_run[i] = 0.f;
#pragma unroll
        for (int j = 0; j < 4; j++) o[i][j] = 0.f;
    }

    for (int kt = 0; kt < SEQ / 64; kt++) {
        __syncthreads();
#pragma unroll
        for (int r = 0; r < 4; r++) {
            int s  = tid + r * 256;
            int d  = s >> 4;
            int c4 = s & 15;
            *(float4*)&Ks[d * 64 + c4 * 4] =
                *(const float4*)&Kbase[d * SEQ + kt * 64 + c4 * 4];
        }
        const float4* vsrc = (const float4*)(Vbase + kt * 64 * DK);
#pragma unroll
        for (int r = 0; r < 4; r++) {
            int s = tid + r * 256;
            ((float4*)Vs)[s] = vsrc[s];
        }
        __syncthreads();

        float sc[4][4];
#pragma unroll
        for (int i = 0; i < 4; i++)
#pragma unroll
            for (int j = 0; j < 4; j++) sc[i][j] = 0.f;

#pragma unroll 16
        for (int d = 0; d < 64; d++) {
            float qv[4], kv[4];
#pragma unroll
            for (int i = 0; i < 4; i++) qv[i] = Qs[(ty * 4 + i) * 64 + d];
            *(float4*)kv = *(float4*)&Ks[d * 64 + tx * 4];
#pragma unroll
            for (int i = 0; i < 4; i++)
#pragma unroll
                for (int j = 0; j < 4; j++)
                    sc[i][j] += qv[i] * kv[j];
        }

#pragma unroll
        for (int i = 0; i < 4; i++) {
            int4 mv = *(const int4*)(Mbase + (ty * 4 + i) * SEQ + kt * 64 + tx * 4);
            if (mv.x == 0) sc[i][0] = -1e30f;
            if (mv.y == 0) sc[i][1] = -1e30f;
            if (mv.z == 0) sc[i][2] = -1e30f;
            if (mv.w == 0) sc[i][3] = -1e30f;
        }

        float mx[4];
#pragma unroll
        for (int i = 0; i < 4; i++) {
            mx[i] = fmaxf(fmaxf(sc[i][0], sc[i][1]), fmaxf(sc[i][2], sc[i][3]));
            for (int off = 1; off < 16; off <<= 1)
                mx[i] = fmaxf(mx[i], __shfl_xor_sync(0xffffffffu, mx[i], off));
        }

        float pr[4][4], rs[4], scl[4];
#pragma unroll
        for (int i = 0; i < 4; i++) {
            float mnew = fmaxf(m_run[i], mx[i]);
            scl[i] = __expf(m_run[i] - mnew);
            m_run[i] = mnew;
            float s0 = 0.f;
#pragma unroll
            for (int j = 0; j < 4; j++) {
                pr[i][j] = __expf(sc[i][j] - mnew);
                s0 += pr[i][j];
            }
            rs[i] = s0;
        }
#pragma unroll
        for (int i = 0; i < 4; i++) {
            for (int off = 1; off < 16; off <<= 1)
                rs[i] += __shfl_xor_sync(0xffffffffu, rs[i], off);
        }
#pragma unroll
        for (int i = 0; i < 4; i++) {
            l_run[i] = l_run[i] * scl[i] + rs[i];
#pragma unroll
            for (int j = 0; j < 4; j++) o[i][j] *= scl[i];
        }

#pragma unroll
        for (int i = 0; i < 4; i++)
            *(float4*)&Ps[(ty * 4 + i) * PSTR + tx * 4] = *(float4*)&pr[i][0];
        __syncthreads();

#pragma unroll 16
        for (int j = 0; j < 64; j++) {
            float pv[4], vv[4];
#pragma unroll
            for (int i = 0; i < 4; i++) pv[i] = Ps[(ty * 4 + i) * PSTR + j];
            *(float4*)vv = *(float4*)&Vs[j * 64 + tx * 4];
#pragma unroll
            for (int i = 0; i < 4; i++)
#pragma unroll
                for (int jj = 0; jj < 4; jj++)
                    o[i][jj] += pv[i] * vv[jj];
        }
    }

    const int h    = bh & (NH - 1);
    const int srow = qt * 64 + ty * 4;
    float* obase = Out + (b * SEQ + srow) * DM + h * DK + tx * 4;
#pragma unroll
    for (int i = 0; i < 4; i++) {
        float inv = (l_run[i] > 0.f) ? 1.f / l_run[i] : 0.f;
        float4 r;
        r.x = o[i][0] * inv;
        r.y = o[i][1] * inv;
        r.z = o[i][2] * inv;
        r.w = o[i][3] * inv;
        *(float4*)&obase[i * DM] = r;
    }
}

// ---------------- launch ----------------
extern "C" void kernel_launch(void* const* d_in, const int* in_sizes, int n_in,
                              void* d_out, int out_size)
{
    const float* q    = (const float*)d_in[0];
    const float* k    = (const float*)d_in[1];
    const float* v    = (const float*)d_in[2];
    const int*   mask = (const int*)  d_in[3];
    const float* wq   = (const float*)d_in[4];
    const float* bq   = (const float*)d_in[5];
    const float* wk   = (const float*)d_in[6];
    const float* wv   = (const float*)d_in[7];
    const float* bv   = (const float*)d_in[8];
    const float* wf   = (const float*)d_in[9];
    const float* bf   = (const float*)d_in[10];
    float* out = (float*)d_out;

    float *Qh, *KhT, *Vh, *At;
    cudaGetSymbolAddress((void**)&Qh,  g_Qh);
    cudaGetSymbolAddress((void**)&KhT, g_KhT);
    cudaGetSymbolAddress((void**)&Vh,  g_Vh);
    cudaGetSymbolAddress((void**)&At,  g_At);

    cudaFuncSetAttribute(tc_gemm,
                         cudaFuncAttributeMaxDynamicSharedMemorySize, SMEM_GEMM);
    size_t smem_attn = (3 * 64 * 64 + 64 * PSTR) * sizeof(float);
    cudaFuncSetAttribute(attn_kernel,
                         cudaFuncAttributeMaxDynamicSharedMemorySize, (int)smem_attn);

    dim3 ggrid(DM / 128, MTOT / 128);   // (8, 32)

    tc_gemm<<<ggrid, 256, SMEM_GEMM>>>(q, wq, bq,      Qh,  1);
    tc_gemm<<<ggrid, 256, SMEM_GEMM>>>(k, wk, nullptr, KhT, 2);
    tc_gemm<<<ggrid, 256, SMEM_GEMM>>>(v, wv, bv,      Vh,  3);

    attn_kernel<<<dim3(SEQ / 64, BATCH * NH), 256, smem_attn>>>(Qh, KhT, Vh, mask, At);

    tc_gemm<<<ggrid, 256, SMEM_GEMM>>>(At, wf, bf, out, 0);
}

// round 9
// speedup vs baseline: 1.5143x; 1.5143x over previous
#include <cuda_runtime.h>
#include <cuda_bf16.h>
#include <math.h>
#include <stdint.h>

// Problem constants
#define BATCH 2
#define SEQ   2048
#define DM    1024
#define NH    16
#define DK    64
#define MTOT  (BATCH*SEQ)       // 4096

// ---------------- scratch (no allocations allowed) ----------------
__device__ float g_Qh [BATCH*NH*SEQ*DK];   // [b*h][s][dk], pre-scaled by 1/8
__device__ float g_KhT[BATCH*NH*DK*SEQ];   // [b*h][dk][s]
__device__ float g_Vh [BATCH*NH*SEQ*DK];   // [b*h][s][dk]
__device__ float g_At [MTOT*DM];           // attention output, [b*s][h*dk]

// hi/lo bf16 copies (activations reused per-GEMM; weights pre-transposed [n][k])
__device__ __nv_bfloat16 g_Xhi[MTOT*DM];
__device__ __nv_bfloat16 g_Xlo[MTOT*DM];
__device__ __nv_bfloat16 g_WhT[4][DM*DM];
__device__ __nv_bfloat16 g_WlT[4][DM*DM];

__device__ __forceinline__ uint32_t smem_u32(const void* p) {
    uint32_t a;
    asm("{ .reg .u64 t; cvta.to.shared.u64 t, %1; cvt.u32.u64 %0, t; }"
        : "=r"(a) : "l"(p));
    return a;
}

#define CP16(dst_u32, src_ptr) \
    asm volatile("cp.async.ca.shared.global [%0], [%1], 16;" \
                 :: "r"(dst_u32), "l"((uint64_t)__cvta_generic_to_global(src_ptr)) : "memory")
#define CP_COMMIT() asm volatile("cp.async.commit_group;" ::: "memory")
#define CP_WAIT1()  asm volatile("cp.async.wait_group 1;" ::: "memory")

__device__ __forceinline__ void split2(float a, float b, uint32_t& hi, uint32_t& lo) {
    __nv_bfloat162 h = __float22bfloat162_rn(make_float2(a, b));
    float2 hf = __bfloat1622float2(h);
    __nv_bfloat162 l = __float22bfloat162_rn(make_float2(a - hf.x, b - hf.y));
    hi = *(uint32_t*)&h;
    lo = *(uint32_t*)&l;
}

__device__ __forceinline__ void mma16816(float* c, const uint32_t* a, const uint32_t* b) {
    asm volatile(
        "mma.sync.aligned.m16n8k16.row.col.f32.bf16.bf16.f32 "
        "{%0,%1,%2,%3},{%4,%5,%6,%7},{%8,%9},{%0,%1,%2,%3};"
        : "+f"(c[0]), "+f"(c[1]), "+f"(c[2]), "+f"(c[3])
        : "r"(a[0]), "r"(a[1]), "r"(a[2]), "r"(a[3]), "r"(b[0]), "r"(b[1]));
}

// ---------------- conversion pre-passes ----------------
// activations: X fp32 [4096][1024] -> Xhi/Xlo bf16, same layout
__global__ __launch_bounds__(256)
void conv_act(const float* __restrict__ X,
              __nv_bfloat16* __restrict__ Xhi, __nv_bfloat16* __restrict__ Xlo)
{
    int idx = blockIdx.x * 256 + threadIdx.x;       // float4 index, 1M total
    float4 x = ((const float4*)X)[idx];
    uint32_t h0, l0, h1, l1;
    split2(x.x, x.y, h0, l0);
    split2(x.z, x.w, h1, l1);
    ((uint2*)Xhi)[idx] = make_uint2(h0, h1);
    ((uint2*)Xlo)[idx] = make_uint2(l0, l1);
}

// weights: W fp32 [k][n] (1024x1024) -> WhT/WlT bf16 [n][k] (transposed)
__global__ __launch_bounds__(256)
void conv_w(const float* __restrict__ W,
            __nv_bfloat16* __restrict__ WhT, __nv_bfloat16* __restrict__ WlT)
{
    __shared__ float ts[32][33];
    const int tx = threadIdx.x, ty = threadIdx.y;   // (32, 8)
    const int kt = blockIdx.y * 32, nt = blockIdx.x * 32;
#pragma unroll
    for (int i = 0; i < 4; i++)
        ts[ty + 8 * i][tx] = W[(size_t)(kt + ty + 8 * i) * DM + nt + tx];
    __syncthreads();
#pragma unroll
    for (int i = 0; i < 4; i++) {
        int n = nt + ty + 8 * i;
        int k = kt + tx;
        float v = ts[tx][ty + 8 * i];
        __nv_bfloat16 h = __float2bfloat16(v);
        __nv_bfloat16 l = __float2bfloat16(v - __bfloat162float(h));
        WhT[(size_t)n * DM + k] = h;
        WlT[(size_t)n * DM + k] = l;
    }
}

// ==================== HMMA bf16 GEMM (pre-converted inputs) ====================
// Y(4096x1024) = X @ W (+bias). CTA tile 128x128, 8 warps 2(M)x4(N), warp 64x32.
// 48 block-iterations: pass 0: Ah*Bh, pass 1: Ah*Bl, pass 2: Al*Bh; K-blocks of 64.
// cp.async double-buffered staging, tiles bf16 [row][k] with ASTR stride.
#define ASTR  72
#define TILEB (128 * ASTR * 2)        // 18432 bytes per tile
#define STAGE (2 * TILEB)             // A + B per stage
#define SMEM_GEMM (2 * STAGE)         // 73728

__device__ __forceinline__ void store1(float* __restrict__ Y,
                                       const float* __restrict__ bias,
                                       int mode, int m, int n, float v)
{
    if (bias) v += bias[n];
    if (mode == 1) v *= 0.125f;
    size_t idx;
    if (mode == 0) {
        idx = (size_t)m * DM + n;
    } else {
        int bq = m >> 11, sq = m & (SEQ - 1);
        int h  = n >> 6,  dk = n & (DK - 1);
        if (mode == 2) idx = (size_t)((bq * NH + h) * DK + dk) * SEQ + sq;
        else           idx = (size_t)((bq * NH + h) * SEQ + sq) * DK + dk;
    }
    Y[idx] = v;
}

__global__ __launch_bounds__(256)
void tc_gemm(const __nv_bfloat16* __restrict__ Xhi, const __nv_bfloat16* __restrict__ Xlo,
             const __nv_bfloat16* __restrict__ WhT, const __nv_bfloat16* __restrict__ WlT,
             const float* __restrict__ bias, float* __restrict__ Y, int mode)
{
    extern __shared__ char sm[];
    const int tid  = threadIdx.x;
    const int wid  = tid >> 5;
    const int lane = tid & 31;
    const int wm   = wid >> 2;
    const int wn   = wid & 3;
    const int bm   = blockIdx.y * 128;
    const int bn   = blockIdx.x * 128;
    const uint32_t sb = smem_u32(sm);

    // cp.async staging map: row = tid>>1 (0..127), half-range = (tid&1)*32, 4x16B each tile
    const int arow = tid >> 1;
    const int acol = (tid & 1) * 32;
    const uint32_t sdA = sb + (uint32_t)(arow * ASTR + acol) * 2;
    const uint32_t sdB = sdA + TILEB;

    float acc[4][4][4];
#pragma unroll
    for (int i = 0; i < 4; i++)
#pragma unroll
        for (int j = 0; j < 4; j++)
#pragma unroll
            for (int r = 0; r < 4; r++) acc[i][j][r] = 0.f;

    const __nv_bfloat16* Asrc0 = Xhi + (size_t)(bm + arow) * DM + acol;
    const __nv_bfloat16* Asrc2 = Xlo + (size_t)(bm + arow) * DM + acol;
    const __nv_bfloat16* Bsrc0 = WhT + (size_t)(bn + arow) * DM + acol;
    const __nv_bfloat16* Bsrc1 = WlT + (size_t)(bn + arow) * DM + acol;

    // stage iteration `it` into buffer `buf`
    auto stage = [&](int buf, int it) {
        const int pass = it >> 4;
        const int k0   = (it & 15) * 64;
        const __nv_bfloat16* As = (pass == 2) ? Asrc2 : Asrc0;
        const __nv_bfloat16* Bs = (pass == 1) ? Bsrc1 : Bsrc0;
        const uint32_t dA = sdA + buf * STAGE;
        const uint32_t dB = sdB + buf * STAGE;
#pragma unroll
        for (int i = 0; i < 4; i++) {
            CP16(dA + i * 16, As + k0 + i * 8);
            CP16(dB + i * 16, Bs + k0 + i * 8);
        }
    };

    stage(0, 0);
    CP_COMMIT();

    const int r4 = lane >> 2;
    const int c4 = (lane & 3) * 2;

    for (int it = 0; it < 48; it++) {
        const int cur = it & 1;
        if (it + 1 < 48) stage(cur ^ 1, it + 1);
        CP_COMMIT();
        CP_WAIT1();
        __syncthreads();

        const __nv_bfloat16* A = (const __nv_bfloat16*)(sm + cur * STAGE);
        const __nv_bfloat16* B = (const __nv_bfloat16*)(sm + cur * STAGE + TILEB);

#pragma unroll
        for (int ks = 0; ks < 4; ks++) {
            const int kc = ks * 16;
            uint32_t af[4][4], bf2[4][2];
#pragma unroll
            for (int mt = 0; mt < 4; mt++) {
                const int m0 = wm * 64 + mt * 16;
                const int o00 = (m0 + r4)     * ASTR + kc + c4;
                const int o10 = (m0 + r4 + 8) * ASTR + kc + c4;
                af[mt][0] = *(const uint32_t*)(A + o00);
                af[mt][1] = *(const uint32_t*)(A + o10);
                af[mt][2] = *(const uint32_t*)(A + o00 + 8);
                af[mt][3] = *(const uint32_t*)(A + o10 + 8);
            }
#pragma unroll
            for (int nt = 0; nt < 4; nt++) {
                const int ob = (wn * 32 + nt * 8 + r4) * ASTR + kc + c4;
                bf2[nt][0] = *(const uint32_t*)(B + ob);
                bf2[nt][1] = *(const uint32_t*)(B + ob + 8);
            }
#pragma unroll
            for (int mt = 0; mt < 4; mt++)
#pragma unroll
                for (int nt = 0; nt < 4; nt++)
                    mma16816(acc[mt][nt], af[mt], bf2[nt]);
        }
        __syncthreads();
    }

    // ---------------- epilogue ----------------
#pragma unroll
    for (int mt = 0; mt < 4; mt++) {
        const int m0 = bm + wm * 64 + mt * 16 + r4;
#pragma unroll
        for (int nt = 0; nt < 4; nt++) {
            const int n0 = bn + wn * 32 + nt * 8 + c4;
            store1(Y, bias, mode, m0,     n0,     acc[mt][nt][0]);
            store1(Y, bias, mode, m0,     n0 + 1, acc[mt][nt][1]);
            store1(Y, bias, mode, m0 + 8, n0,     acc[mt][nt][2]);
            store1(Y, bias, mode, m0 + 8, n0 + 1, acc[mt][nt][3]);
        }
    }
}

// ---------------- flash attention (fp32, online softmax) ----------------
#define PSTR 68

__global__ __launch_bounds__(256)
void attn_kernel(const float* __restrict__ Qh, const float* __restrict__ KhT,
                 const float* __restrict__ Vh, const int* __restrict__ mask,
                 float* __restrict__ Out)
{
    extern __shared__ float smf[];
    float* Qs = smf;
    float* Ks = smf + 64 * 64;
    float* Vs = smf + 2 * 64 * 64;
    float* Ps = smf + 3 * 64 * 64;

    const int tid = threadIdx.x;
    const int tx  = tid & 15;
    const int ty  = tid >> 4;
    const int qt  = blockIdx.x;
    const int bh  = blockIdx.y;
    const int b   = bh >> 4;

    const float* Qbase = Qh  + (bh * SEQ + qt * 64) * DK;
    const float* Kbase = KhT + bh * DK * SEQ;
    const float* Vbase = Vh  + bh * SEQ * DK;
    const int*   Mbase = mask + (b * SEQ + qt * 64) * SEQ;

#pragma unroll
    for (int r = 0; r < 4; r++) {
        int s = tid + r * 256;
        ((float4*)Qs)[s] = ((const float4*)Qbase)[s];
    }

    float m_run[4], l_run[4], o[4][4];
#pragma unroll
    for (int i = 0; i < 4; i++) {
        m_run[i] = -1e38f;
        l_run[i] = 0.f;
#pragma unroll
        for (int j = 0; j < 4; j++) o[i][j] = 0.f;
    }

    for (int kt = 0; kt < SEQ / 64; kt++) {
        __syncthreads();
#pragma unroll
        for (int r = 0; r < 4; r++) {
            int s  = tid + r * 256;
            int d  = s >> 4;
            int c4v = s & 15;
            *(float4*)&Ks[d * 64 + c4v * 4] =
                *(const float4*)&Kbase[d * SEQ + kt * 64 + c4v * 4];
        }
        const float4* vsrc = (const float4*)(Vbase + kt * 64 * DK);
#pragma unroll
        for (int r = 0; r < 4; r++) {
            int s = tid + r * 256;
            ((float4*)Vs)[s] = vsrc[s];
        }
        __syncthreads();

        float sc[4][4];
#pragma unroll
        for (int i = 0; i < 4; i++)
#pragma unroll
            for (int j = 0; j < 4; j++) sc[i][j] = 0.f;

#pragma unroll 16
        for (int d = 0; d < 64; d++) {
            float qv[4], kv[4];
#pragma unroll
            for (int i = 0; i < 4; i++) qv[i] = Qs[(ty * 4 + i) * 64 + d];
            *(float4*)kv = *(float4*)&Ks[d * 64 + tx * 4];
#pragma unroll
            for (int i = 0; i < 4; i++)
#pragma unroll
                for (int j = 0; j < 4; j++)
                    sc[i][j] += qv[i] * kv[j];
        }

#pragma unroll
        for (int i = 0; i < 4; i++) {
            int4 mv = *(const int4*)(Mbase + (ty * 4 + i) * SEQ + kt * 64 + tx * 4);
            if (mv.x == 0) sc[i][0] = -1e30f;
            if (mv.y == 0) sc[i][1] = -1e30f;
            if (mv.z == 0) sc[i][2] = -1e30f;
            if (mv.w == 0) sc[i][3] = -1e30f;
        }

        float mx[4];
#pragma unroll
        for (int i = 0; i < 4; i++) {
            mx[i] = fmaxf(fmaxf(sc[i][0], sc[i][1]), fmaxf(sc[i][2], sc[i][3]));
            for (int off = 1; off < 16; off <<= 1)
                mx[i] = fmaxf(mx[i], __shfl_xor_sync(0xffffffffu, mx[i], off));
        }

        float pr[4][4], rs[4], scl[4];
#pragma unroll
        for (int i = 0; i < 4; i++) {
            float mnew = fmaxf(m_run[i], mx[i]);
            scl[i] = __expf(m_run[i] - mnew);
            m_run[i] = mnew;
            float s0 = 0.f;
#pragma unroll
            for (int j = 0; j < 4; j++) {
                pr[i][j] = __expf(sc[i][j] - mnew);
                s0 += pr[i][j];
            }
            rs[i] = s0;
        }
#pragma unroll
        for (int i = 0; i < 4; i++) {
            for (int off = 1; off < 16; off <<= 1)
                rs[i] += __shfl_xor_sync(0xffffffffu, rs[i], off);
        }
#pragma unroll
        for (int i = 0; i < 4; i++) {
            l_run[i] = l_run[i] * scl[i] + rs[i];
#pragma unroll
            for (int j = 0; j < 4; j++) o[i][j] *= scl[i];
        }

#pragma unroll
        for (int i = 0; i < 4; i++)
            *(float4*)&Ps[(ty * 4 + i) * PSTR + tx * 4] = *(float4*)&pr[i][0];
        __syncthreads();

#pragma unroll 16
        for (int j = 0; j < 64; j++) {
            float pv[4], vv[4];
#pragma unroll
            for (int i = 0; i < 4; i++) pv[i] = Ps[(ty * 4 + i) * PSTR + j];
            *(float4*)vv = *(float4*)&Vs[j * 64 + tx * 4];
#pragma unroll
            for (int i = 0; i < 4; i++)
#pragma unroll
                for (int jj = 0; jj < 4; jj++)
                    o[i][jj] += pv[i] * vv[jj];
        }
    }

    const int h    = bh & (NH - 1);
    const int srow = qt * 64 + ty * 4;
    float* obase = Out + (b * SEQ + srow) * DM + h * DK + tx * 4;
#pragma unroll
    for (int i = 0; i < 4; i++) {
        float inv = (l_run[i] > 0.f) ? 1.f / l_run[i] : 0.f;
        float4 r;
        r.x = o[i][0] * inv;
        r.y = o[i][1] * inv;
        r.z = o[i][2] * inv;
        r.w = o[i][3] * inv;
        *(float4*)&obase[i * DM] = r;
    }
}

// ---------------- launch ----------------
extern "C" void kernel_launch(void* const* d_in, const int* in_sizes, int n_in,
                              void* d_out, int out_size)
{
    const float* q    = (const float*)d_in[0];
    const float* k    = (const float*)d_in[1];
    const float* v    = (const float*)d_in[2];
    const int*   mask = (const int*)  d_in[3];
    const float* wq   = (const float*)d_in[4];
    const float* bq   = (const float*)d_in[5];
    const float* wk   = (const float*)d_in[6];
    const float* wv   = (const float*)d_in[7];
    const float* bv   = (const float*)d_in[8];
    const float* wf   = (const float*)d_in[9];
    const float* bf   = (const float*)d_in[10];
    float* out = (float*)d_out;

    float *Qh, *KhT, *Vh, *At;
    cudaGetSymbolAddress((void**)&Qh,  g_Qh);
    cudaGetSymbolAddress((void**)&KhT, g_KhT);
    cudaGetSymbolAddress((void**)&Vh,  g_Vh);
    cudaGetSymbolAddress((void**)&At,  g_At);
    __nv_bfloat16 *Xhi, *Xlo, *WhT, *WlT;
    cudaGetSymbolAddress((void**)&Xhi, g_Xhi);
    cudaGetSymbolAddress((void**)&Xlo, g_Xlo);
    cudaGetSymbolAddress((void**)&WhT, g_WhT);
    cudaGetSymbolAddress((void**)&WlT, g_WlT);

    cudaFuncSetAttribute(tc_gemm,
                         cudaFuncAttributeMaxDynamicSharedMemorySize, SMEM_GEMM);
    size_t smem_attn = (3 * 64 * 64 + 64 * PSTR) * sizeof(float);
    cudaFuncSetAttribute(attn_kernel,
                         cudaFuncAttributeMaxDynamicSharedMemorySize, (int)smem_attn);

    dim3 wgrid(32, 32);
    dim3 wblk(32, 8);
    conv_w<<<wgrid, wblk>>>(wq, WhT + 0 * DM * DM, WlT + 0 * DM * DM);
    conv_w<<<wgrid, wblk>>>(wk, WhT + 1 * DM * DM, WlT + 1 * DM * DM);
    conv_w<<<wgrid, wblk>>>(wv, WhT + 2 * DM * DM, WlT + 2 * DM * DM);
    conv_w<<<wgrid, wblk>>>(wf, WhT + 3 * DM * DM, WlT + 3 * DM * DM);

    dim3 ggrid(DM / 128, MTOT / 128);   // (8, 32)

    conv_act<<<MTOT * DM / 1024, 256>>>(q, Xhi, Xlo);
    tc_gemm<<<ggrid, 256, SMEM_GEMM>>>(Xhi, Xlo, WhT + 0 * DM * DM, WlT + 0 * DM * DM, bq, Qh, 1);

    conv_act<<<MTOT * DM / 1024, 256>>>(k, Xhi, Xlo);
    tc_gemm<<<ggrid, 256, SMEM_GEMM>>>(Xhi, Xlo, WhT + 1 * DM * DM, WlT + 1 * DM * DM, nullptr, KhT, 2);

    conv_act<<<MTOT * DM / 1024, 256>>>(v, Xhi, Xlo);
    tc_gemm<<<ggrid, 256, SMEM_GEMM>>>(Xhi, Xlo, WhT + 2 * DM * DM, WlT + 2 * DM * DM, bv, Vh, 3);

    attn_kernel<<<dim3(SEQ / 64, BATCH * NH), 256, smem_attn>>>(Qh, KhT, Vh, mask, At);

    conv_act<<<MTOT * DM / 1024, 256>>>(At, Xhi, Xlo);
    tc_gemm<<<ggrid, 256, SMEM_GEMM>>>(Xhi, Xlo, WhT + 3 * DM * DM, WlT + 3 * DM * DM, bf, out, 0);
}

// round 10
// speedup vs baseline: 2.2225x; 1.4677x over previous
#include <cuda_runtime.h>
#include <cuda_bf16.h>
#include <math.h>
#include <stdint.h>

// Problem constants
#define BATCH 2
#define SEQ   2048
#define DM    1024
#define NH    16
#define DK    64
#define MTOT  (BATCH*SEQ)       // 4096

// ---------------- scratch (no allocations allowed) ----------------
__device__ float g_At [MTOT*DM];           // attention output, [b*s][h*dk]
__device__ __nv_bfloat16 g_Xhi[MTOT*DM];
__device__ __nv_bfloat16 g_Xlo[MTOT*DM];
__device__ __nv_bfloat16 g_WhT[4][DM*DM];
__device__ __nv_bfloat16 g_WlT[4][DM*DM];
// attention operands (hi/lo bf16): Q,K: [bh][s][dk]; V: transposed [bh][dk][s]
__device__ __nv_bfloat16 g_Qhi[MTOT*DM/16*16];  // 4.19M elems each
__device__ __nv_bfloat16 g_Qlo[MTOT*DM];
__device__ __nv_bfloat16 g_Khi[MTOT*DM];
__device__ __nv_bfloat16 g_Klo[MTOT*DM];
__device__ __nv_bfloat16 g_Vhi[MTOT*DM];
__device__ __nv_bfloat16 g_Vlo[MTOT*DM];

__device__ __forceinline__ uint32_t smem_u32(const void* p) {
    uint32_t a;
    asm("{ .reg .u64 t; cvta.to.shared.u64 t, %1; cvt.u32.u64 %0, t; }"
        : "=r"(a) : "l"(p));
    return a;
}

#define CP16(dst_u32, src_ptr) \
    asm volatile("cp.async.ca.shared.global [%0], [%1], 16;" \
                 :: "r"(dst_u32), "l"((uint64_t)__cvta_generic_to_global(src_ptr)) : "memory")
#define CP_COMMIT() asm volatile("cp.async.commit_group;" ::: "memory")
#define CP_WAIT1()  asm volatile("cp.async.wait_group 1;" ::: "memory")
#define CP_WAIT0()  asm volatile("cp.async.wait_group 0;" ::: "memory")

__device__ __forceinline__ void split2(float a, float b, uint32_t& hi, uint32_t& lo) {
    __nv_bfloat162 h = __float22bfloat162_rn(make_float2(a, b));
    float2 hf = __bfloat1622float2(h);
    __nv_bfloat162 l = __float22bfloat162_rn(make_float2(a - hf.x, b - hf.y));
    hi = *(uint32_t*)&h;
    lo = *(uint32_t*)&l;
}

__device__ __forceinline__ void mma16816(float* c, const uint32_t* a, const uint32_t* b) {
    asm volatile(
        "mma.sync.aligned.m16n8k16.row.col.f32.bf16.bf16.f32 "
        "{%0,%1,%2,%3},{%4,%5,%6,%7},{%8,%9},{%0,%1,%2,%3};"
        : "+f"(c[0]), "+f"(c[1]), "+f"(c[2]), "+f"(c[3])
        : "r"(a[0]), "r"(a[1]), "r"(a[2]), "r"(a[3]), "r"(b[0]), "r"(b[1]));
}

// ---------------- conversion pre-passes ----------------
__global__ __launch_bounds__(256)
void conv_act(const float* __restrict__ X,
              __nv_bfloat16* __restrict__ Xhi, __nv_bfloat16* __restrict__ Xlo)
{
    int idx = blockIdx.x * 256 + threadIdx.x;
    float4 x = ((const float4*)X)[idx];
    uint32_t h0, l0, h1, l1;
    split2(x.x, x.y, h0, l0);
    split2(x.z, x.w, h1, l1);
    ((uint2*)Xhi)[idx] = make_uint2(h0, h1);
    ((uint2*)Xlo)[idx] = make_uint2(l0, l1);
}

__global__ __launch_bounds__(256)
void conv_w(const float* __restrict__ W,
            __nv_bfloat16* __restrict__ WhT, __nv_bfloat16* __restrict__ WlT)
{
    __shared__ float ts[32][33];
    const int tx = threadIdx.x, ty = threadIdx.y;   // (32, 8)
    const int kt = blockIdx.y * 32, nt = blockIdx.x * 32;
#pragma unroll
    for (int i = 0; i < 4; i++)
        ts[ty + 8 * i][tx] = W[(size_t)(kt + ty + 8 * i) * DM + nt + tx];
    __syncthreads();
#pragma unroll
    for (int i = 0; i < 4; i++) {
        int n = nt + ty + 8 * i;
        int k = kt + tx;
        float v = ts[tx][ty + 8 * i];
        __nv_bfloat16 h = __float2bfloat16(v);
        __nv_bfloat16 l = __float2bfloat16(v - __bfloat162float(h));
        WhT[(size_t)n * DM + k] = h;
        WlT[(size_t)n * DM + k] = l;
    }
}

// ==================== HMMA bf16 GEMM ====================
// modes: 0 fp32 plain out; 1 Q->hi/lo bf16 [bh][s][dk] *0.125 (+bias);
//        2 K->hi/lo bf16 [bh][s][dk]; 3 V->hi/lo bf16 TRANSPOSED [bh][dk][s] (+bias)
#define ASTR  72
#define TILEB (128 * ASTR * 2)        // 18432 bytes per tile
#define STAGE (2 * TILEB)
#define SMEM_GEMM (2 * STAGE)         // 73728

__global__ __launch_bounds__(256)
void tc_gemm(const __nv_bfloat16* __restrict__ Xhi, const __nv_bfloat16* __restrict__ Xlo,
             const __nv_bfloat16* __restrict__ WhT, const __nv_bfloat16* __restrict__ WlT,
             const float* __restrict__ bias, float* __restrict__ Yf,
             __nv_bfloat16* __restrict__ Yh, __nv_bfloat16* __restrict__ Yl, int mode)
{
    extern __shared__ char sm[];
    const int tid  = threadIdx.x;
    const int wid  = tid >> 5;
    const int lane = tid & 31;
    const int wm   = wid >> 2;
    const int wn   = wid & 3;
    const int bm   = blockIdx.y * 128;
    const int bn   = blockIdx.x * 128;
    const uint32_t sb = smem_u32(sm);

    const int arow = tid >> 1;
    const int acol = (tid & 1) * 32;
    const uint32_t sdA = sb + (uint32_t)(arow * ASTR + acol) * 2;
    const uint32_t sdB = sdA + TILEB;

    float acc[4][4][4];
#pragma unroll
    for (int i = 0; i < 4; i++)
#pragma unroll
        for (int j = 0; j < 4; j++)
#pragma unroll
            for (int r = 0; r < 4; r++) acc[i][j][r] = 0.f;

    const __nv_bfloat16* Asrc0 = Xhi + (size_t)(bm + arow) * DM + acol;
    const __nv_bfloat16* Asrc2 = Xlo + (size_t)(bm + arow) * DM + acol;
    const __nv_bfloat16* Bsrc0 = WhT + (size_t)(bn + arow) * DM + acol;
    const __nv_bfloat16* Bsrc1 = WlT + (size_t)(bn + arow) * DM + acol;

    auto stage = [&](int buf, int it) {
        const int pass = it >> 4;
        const int k0   = (it & 15) * 64;
        const __nv_bfloat16* As = (pass == 2) ? Asrc2 : Asrc0;
        const __nv_bfloat16* Bs = (pass == 1) ? Bsrc1 : Bsrc0;
        const uint32_t dA = sdA + buf * STAGE;
        const uint32_t dB = sdB + buf * STAGE;
#pragma unroll
        for (int i = 0; i < 4; i++) {
            CP16(dA + i * 16, As + k0 + i * 8);
            CP16(dB + i * 16, Bs + k0 + i * 8);
        }
    };

    stage(0, 0);
    CP_COMMIT();

    const int r4 = lane >> 2;
    const int c4 = (lane & 3) * 2;

    for (int it = 0; it < 48; it++) {
        const int cur = it & 1;
        if (it + 1 < 48) stage(cur ^ 1, it + 1);
        CP_COMMIT();
        CP_WAIT1();
        __syncthreads();

        const __nv_bfloat16* A = (const __nv_bfloat16*)(sm + cur * STAGE);
        const __nv_bfloat16* B = (const __nv_bfloat16*)(sm + cur * STAGE + TILEB);

#pragma unroll
        for (int ks = 0; ks < 4; ks++) {
            const int kc = ks * 16;
            uint32_t af[4][4], bf2[4][2];
#pragma unroll
            for (int mt = 0; mt < 4; mt++) {
                const int m0 = wm * 64 + mt * 16;
                const int o00 = (m0 + r4)     * ASTR + kc + c4;
                const int o10 = (m0 + r4 + 8) * ASTR + kc + c4;
                af[mt][0] = *(const uint32_t*)(A + o00);
                af[mt][1] = *(const uint32_t*)(A + o10);
                af[mt][2] = *(const uint32_t*)(A + o00 + 8);
                af[mt][3] = *(const uint32_t*)(A + o10 + 8);
            }
#pragma unroll
            for (int nt = 0; nt < 4; nt++) {
                const int ob = (wn * 32 + nt * 8 + r4) * ASTR + kc + c4;
                bf2[nt][0] = *(const uint32_t*)(B + ob);
                bf2[nt][1] = *(const uint32_t*)(B + ob + 8);
            }
#pragma unroll
            for (int mt = 0; mt < 4; mt++)
#pragma unroll
                for (int nt = 0; nt < 4; nt++)
                    mma16816(acc[mt][nt], af[mt], bf2[nt]);
        }
        __syncthreads();
    }

    // ---------------- epilogue ----------------
#pragma unroll
    for (int mt = 0; mt < 4; mt++) {
#pragma unroll
        for (int rr = 0; rr < 2; rr++) {
            const int m  = bm + wm * 64 + mt * 16 + r4 + rr * 8;
            const int bq = m >> 11, sq = m & (SEQ - 1);
#pragma unroll
            for (int nt = 0; nt < 4; nt++) {
                const int n = bn + wn * 32 + nt * 8 + c4;
                float v0 = acc[mt][nt][rr * 2], v1 = acc[mt][nt][rr * 2 + 1];
                if (bias) { v0 += bias[n]; v1 += bias[n + 1]; }
                if (mode == 1) { v0 *= 0.125f; v1 *= 0.125f; }
                if (mode == 0) {
                    *(float2*)&Yf[(size_t)m * DM + n] = make_float2(v0, v1);
                } else if (mode == 3) {
                    const int hh = n >> 6, dk = n & 63;
                    size_t i0 = ((size_t)(bq * NH + hh) * DK + dk) * SEQ + sq;
                    __nv_bfloat16 h0 = __float2bfloat16(v0);
                    __nv_bfloat16 h1 = __float2bfloat16(v1);
                    Yh[i0]       = h0;
                    Yh[i0 + SEQ] = h1;
                    Yl[i0]       = __float2bfloat16(v0 - __bfloat162float(h0));
                    Yl[i0 + SEQ] = __float2bfloat16(v1 - __bfloat162float(h1));
                } else {
                    uint32_t hi, lo;
                    split2(v0, v1, hi, lo);
                    const int hh = n >> 6, dk = n & 63;
                    size_t idx = ((size_t)(bq * NH + hh) * SEQ + sq) * DK + dk;
                    *(uint32_t*)&Yh[idx] = hi;
                    *(uint32_t*)&Yl[idx] = lo;
                }
            }
        }
    }
}

// ==================== HMMA flash attention ====================
// grid (16, 32): Q tile 128 rows, 8 warps x 16 rows. K-tiles of 64, 32 iters.
// K/V hi+lo tiles double-buffered via cp.async. Q frags register-resident.
#define ATSTR 72
#define ATILE (64 * ATSTR * 2)    // 9216 B
#define ASTAGE (4 * ATILE)        // 36864: Khi, Klo, Vhi, Vlo
#define QTILE (128 * ATSTR * 2)   // 18432
#define SMEM_ATT (2 * ASTAGE)     // 73728

__global__ __launch_bounds__(256)
void attn_tc(const __nv_bfloat16* __restrict__ Qhi_, const __nv_bfloat16* __restrict__ Qlo_,
             const __nv_bfloat16* __restrict__ Khi_, const __nv_bfloat16* __restrict__ Klo_,
             const __nv_bfloat16* __restrict__ Vhi_, const __nv_bfloat16* __restrict__ Vlo_,
             const int* __restrict__ mask, float* __restrict__ Out)
{
    extern __shared__ char sm[];
    const int tid  = threadIdx.x;
    const int wid  = tid >> 5;
    const int lane = tid & 31;
    const int r4   = lane >> 2;
    const int c4   = (lane & 3) * 2;
    const int qt   = blockIdx.x;
    const int bh   = blockIdx.y;
    const int b    = bh >> 4;
    const int h    = bh & 15;
    const uint32_t sb = smem_u32(sm);

    // ---- stage Q hi/lo (128x64) into buf0 area, load frags to registers ----
#pragma unroll
    for (int i = 0; i < 4; i++) {
        int c   = tid + i * 256;
        int row = c >> 3;
        int off = (c & 7) * 8;
        const __nv_bfloat16* s0 = Qhi_ + ((size_t)bh * SEQ + qt * 128 + row) * DK + off;
        const __nv_bfloat16* s1 = Qlo_ + ((size_t)bh * SEQ + qt * 128 + row) * DK + off;
        uint32_t d = sb + (uint32_t)(row * ATSTR + off) * 2;
        CP16(d, s0);
        CP16(d + QTILE, s1);
    }
    CP_COMMIT();
    CP_WAIT0();
    __syncthreads();

    uint32_t qh[4][4], ql[4][4];
    {
        const __nv_bfloat16* Qh = (const __nv_bfloat16*)sm;
        const __nv_bfloat16* Ql = (const __nv_bfloat16*)(sm + QTILE);
#pragma unroll
        for (int ks = 0; ks < 4; ks++) {
            const int o00 = (wid * 16 + r4) * ATSTR + ks * 16 + c4;
            const int o10 = o00 + 8 * ATSTR;
            qh[ks][0] = *(const uint32_t*)(Qh + o00);
            qh[ks][1] = *(const uint32_t*)(Qh + o10);
            qh[ks][2] = *(const uint32_t*)(Qh + o00 + 8);
            qh[ks][3] = *(const uint32_t*)(Qh + o10 + 8);
            ql[ks][0] = *(const uint32_t*)(Ql + o00);
            ql[ks][1] = *(const uint32_t*)(Ql + o10);
            ql[ks][2] = *(const uint32_t*)(Ql + o00 + 8);
            ql[ks][3] = *(const uint32_t*)(Ql + o10 + 8);
        }
    }
    __syncthreads();   // all warps done reading Q area before K/V staging reuses it

    // per-thread stage of one K-tile pair + V-tile pair chunk set
    auto stageKV = [&](int buf, int kt) {
        const int row = tid >> 2;              // 0..63
        const int off = ((tid & 3) * 2) * 8;   // halves: 0,16,32,48
        uint32_t d = sb + buf * ASTAGE + (uint32_t)(row * ATSTR + off) * 2;
        const __nv_bfloat16* k0 = Khi_ + ((size_t)bh * SEQ + kt * 64 + row) * DK + off;
        const __nv_bfloat16* k1 = Klo_ + ((size_t)bh * SEQ + kt * 64 + row) * DK + off;
        const __nv_bfloat16* v0 = Vhi_ + ((size_t)bh * DK + row) * SEQ + kt * 64 + off;
        const __nv_bfloat16* v1 = Vlo_ + ((size_t)bh * DK + row) * SEQ + kt * 64 + off;
        CP16(d,                  k0);     CP16(d + 16,              k0 + 8);
        CP16(d + ATILE,          k1);     CP16(d + ATILE + 16,      k1 + 8);
        CP16(d + 2 * ATILE,      v0);     CP16(d + 2 * ATILE + 16,  v0 + 8);
        CP16(d + 3 * ATILE,      v1);     CP16(d + 3 * ATILE + 16,  v1 + 8);
    };

    stageKV(0, 0);
    CP_COMMIT();

    float oacc[8][4];
#pragma unroll
    for (int nb = 0; nb < 8; nb++)
#pragma unroll
        for (int r = 0; r < 4; r++) oacc[nb][r] = 0.f;
    float mrun0 = -1e30f, mrun1 = -1e30f, lrun0 = 0.f, lrun1 = 0.f;

    const int ro0 = qt * 128 + wid * 16 + r4;
    const int* mrow = mask + ((size_t)b * SEQ + ro0) * SEQ;

    for (int kt = 0; kt < 32; kt++) {
        const int cur = kt & 1;
        if (kt + 1 < 32) { stageKV(cur ^ 1, kt + 1); CP_COMMIT(); CP_WAIT1(); }
        else             { CP_WAIT0(); }
        __syncthreads();

        const __nv_bfloat16* Kh = (const __nv_bfloat16*)(sm + cur * ASTAGE);
        const __nv_bfloat16* Kl = (const __nv_bfloat16*)(sm + cur * ASTAGE + ATILE);
        const __nv_bfloat16* Vh = (const __nv_bfloat16*)(sm + cur * ASTAGE + 2 * ATILE);
        const __nv_bfloat16* Vl = (const __nv_bfloat16*)(sm + cur * ASTAGE + 3 * ATILE);

        // ---- scores: S = Q K^T (3-pass) ----
        float sacc[8][4];
#pragma unroll
        for (int nb = 0; nb < 8; nb++)
#pragma unroll
            for (int r = 0; r < 4; r++) sacc[nb][r] = 0.f;

#pragma unroll
        for (int ks = 0; ks < 4; ks++) {
            const int kc = ks * 16;
            uint32_t kh2[8][2], kl2[8][2];
#pragma unroll
            for (int nb = 0; nb < 8; nb++) {
                const int ob = (nb * 8 + r4) * ATSTR + kc + c4;
                kh2[nb][0] = *(const uint32_t*)(Kh + ob);
                kh2[nb][1] = *(const uint32_t*)(Kh + ob + 8);
                kl2[nb][0] = *(const uint32_t*)(Kl + ob);
                kl2[nb][1] = *(const uint32_t*)(Kl + ob + 8);
            }
#pragma unroll
            for (int nb = 0; nb < 8; nb++) mma16816(sacc[nb], qh[ks], kh2[nb]);
#pragma unroll
            for (int nb = 0; nb < 8; nb++) mma16816(sacc[nb], qh[ks], kl2[nb]);
#pragma unroll
            for (int nb = 0; nb < 8; nb++) mma16816(sacc[nb], ql[ks], kh2[nb]);
        }

        // ---- mask ----
        const int* mc = mrow + kt * 64;
#pragma unroll
        for (int nb = 0; nb < 8; nb++) {
            int2 mv0 = *(const int2*)(mc + nb * 8 + c4);
            int2 mv1 = *(const int2*)(mc + 8 * SEQ + nb * 8 + c4);
            if (mv0.x == 0) sacc[nb][0] = -1e30f;
            if (mv0.y == 0) sacc[nb][1] = -1e30f;
            if (mv1.x == 0) sacc[nb][2] = -1e30f;
            if (mv1.y == 0) sacc[nb][3] = -1e30f;
        }

        // ---- online softmax (rows r4, r4+8; 4-lane groups share a row) ----
        float mx0 = -1e30f, mx1 = -1e30f;
#pragma unroll
        for (int nb = 0; nb < 8; nb++) {
            mx0 = fmaxf(mx0, fmaxf(sacc[nb][0], sacc[nb][1]));
            mx1 = fmaxf(mx1, fmaxf(sacc[nb][2], sacc[nb][3]));
        }
        mx0 = fmaxf(mx0, __shfl_xor_sync(0xffffffffu, mx0, 1));
        mx0 = fmaxf(mx0, __shfl_xor_sync(0xffffffffu, mx0, 2));
        mx1 = fmaxf(mx1, __shfl_xor_sync(0xffffffffu, mx1, 1));
        mx1 = fmaxf(mx1, __shfl_xor_sync(0xffffffffu, mx1, 2));

        const float mn0 = fmaxf(mrun0, mx0);
        const float mn1 = fmaxf(mrun1, mx1);
        const float scl0 = __expf(mrun0 - mn0);
        const float scl1 = __expf(mrun1 - mn1);
        mrun0 = mn0; mrun1 = mn1;

        float rs0 = 0.f, rs1 = 0.f;
#pragma unroll
        for (int nb = 0; nb < 8; nb++) {
            sacc[nb][0] = __expf(sacc[nb][0] - mn0);
            sacc[nb][1] = __expf(sacc[nb][1] - mn0);
            sacc[nb][2] = __expf(sacc[nb][2] - mn1);
            sacc[nb][3] = __expf(sacc[nb][3] - mn1);
            rs0 += sacc[nb][0] + sacc[nb][1];
            rs1 += sacc[nb][2] + sacc[nb][3];
        }
        rs0 += __shfl_xor_sync(0xffffffffu, rs0, 1);
        rs0 += __shfl_xor_sync(0xffffffffu, rs0, 2);
        rs1 += __shfl_xor_sync(0xffffffffu, rs1, 1);
        rs1 += __shfl_xor_sync(0xffffffffu, rs1, 2);
        lrun0 = lrun0 * scl0 + rs0;
        lrun1 = lrun1 * scl1 + rs1;

#pragma unroll
        for (int nb = 0; nb < 8; nb++) {
            oacc[nb][0] *= scl0; oacc[nb][1] *= scl0;
            oacc[nb][2] *= scl1; oacc[nb][3] *= scl1;
        }

        // ---- P -> hi/lo A-fragments (accumulator layout == A-frag layout) ----
        uint32_t pah[4][4], pal[4][4];
#pragma unroll
        for (int ks = 0; ks < 4; ks++) {
            split2(sacc[2 * ks][0],     sacc[2 * ks][1],     pah[ks][0], pal[ks][0]);
            split2(sacc[2 * ks][2],     sacc[2 * ks][3],     pah[ks][1], pal[ks][1]);
            split2(sacc[2 * ks + 1][0], sacc[2 * ks + 1][1], pah[ks][2], pal[ks][2]);
            split2(sacc[2 * ks + 1][2], sacc[2 * ks + 1][3], pah[ks][3], pal[ks][3]);
        }

        // ---- O += P V (3-pass), B from V^T tile [dv][j] ----
#pragma unroll
        for (int ks = 0; ks < 4; ks++) {
            const int kc = ks * 16;
            uint32_t vh2[8][2], vl2[8][2];
#pragma unroll
            for (int nb = 0; nb < 8; nb++) {
                const int ob = (nb * 8 + r4) * ATSTR + kc + c4;
                vh2[nb][0] = *(const uint32_t*)(Vh + ob);
                vh2[nb][1] = *(const uint32_t*)(Vh + ob + 8);
                vl2[nb][0] = *(const uint32_t*)(Vl + ob);
                vl2[nb][1] = *(const uint32_t*)(Vl + ob + 8);
            }
#pragma unroll
            for (int nb = 0; nb < 8; nb++) mma16816(oacc[nb], pah[ks], vh2[nb]);
#pragma unroll
            for (int nb = 0; nb < 8; nb++) mma16816(oacc[nb], pah[ks], vl2[nb]);
#pragma unroll
            for (int nb = 0; nb < 8; nb++) mma16816(oacc[nb], pal[ks], vh2[nb]);
        }
        __syncthreads();
    }

    // ---- epilogue: normalize, write [b*s][h*dk] fp32 ----
    const float inv0 = (lrun0 > 0.f) ? 1.f / lrun0 : 0.f;
    const float inv1 = (lrun1 > 0.f) ? 1.f / lrun1 : 0.f;
    float* o0 = Out + ((size_t)b * SEQ + ro0) * DM + h * DK;
#pragma unroll
    for (int nb = 0; nb < 8; nb++) {
        *(float2*)(o0 + nb * 8 + c4) =
            make_float2(oacc[nb][0] * inv0, oacc[nb][1] * inv0);
        *(float2*)(o0 + (size_t)8 * DM + nb * 8 + c4) =
            make_float2(oacc[nb][2] * inv1, oacc[nb][3] * inv1);
    }
}

// ---------------- launch ----------------
extern "C" void kernel_launch(void* const* d_in, const int* in_sizes, int n_in,
                              void* d_out, int out_size)
{
    const float* q    = (const float*)d_in[0];
    const float* k    = (const float*)d_in[1];
    const float* v    = (const float*)d_in[2];
    const int*   mask = (const int*)  d_in[3];
    const float* wq   = (const float*)d_in[4];
    const float* bq   = (const float*)d_in[5];
    const float* wk   = (const float*)d_in[6];
    const float* wv   = (const float*)d_in[7];
    const float* bv   = (const float*)d_in[8];
    const float* wf   = (const float*)d_in[9];
    const float* bf   = (const float*)d_in[10];
    float* out = (float*)d_out;

    float* At;
    cudaGetSymbolAddress((void**)&At, g_At);
    __nv_bfloat16 *Xhi, *Xlo, *WhT, *WlT, *Qhi, *Qlo, *Khi, *Klo, *Vhi, *Vlo;
    cudaGetSymbolAddress((void**)&Xhi, g_Xhi);
    cudaGetSymbolAddress((void**)&Xlo, g_Xlo);
    cudaGetSymbolAddress((void**)&WhT, g_WhT);
    cudaGetSymbolAddress((void**)&WlT, g_WlT);
    cudaGetSymbolAddress((void**)&Qhi, g_Qhi);
    cudaGetSymbolAddress((void**)&Qlo, g_Qlo);
    cudaGetSymbolAddress((void**)&Khi, g_Khi);
    cudaGetSymbolAddress((void**)&Klo, g_Klo);
    cudaGetSymbolAddress((void**)&Vhi, g_Vhi);
    cudaGetSymbolAddress((void**)&Vlo, g_Vlo);

    cudaFuncSetAttribute(tc_gemm,
                         cudaFuncAttributeMaxDynamicSharedMemorySize, SMEM_GEMM);
    cudaFuncSetAttribute(attn_tc,
                         cudaFuncAttributeMaxDynamicSharedMemorySize, SMEM_ATT);

    dim3 wgrid(32, 32);
    dim3 wblk(32, 8);
    conv_w<<<wgrid, wblk>>>(wq, WhT + 0 * DM * DM, WlT + 0 * DM * DM);
    conv_w<<<wgrid, wblk>>>(wk, WhT + 1 * DM * DM, WlT + 1 * DM * DM);
    conv_w<<<wgrid, wblk>>>(wv, WhT + 2 * DM * DM, WlT + 2 * DM * DM);
    conv_w<<<wgrid, wblk>>>(wf, WhT + 3 * DM * DM, WlT + 3 * DM * DM);

    dim3 ggrid(DM / 128, MTOT / 128);   // (8, 32)

    conv_act<<<MTOT * DM / 1024, 256>>>(q, Xhi, Xlo);
    tc_gemm<<<ggrid, 256, SMEM_GEMM>>>(Xhi, Xlo, WhT + 0 * DM * DM, WlT + 0 * DM * DM,
                                       bq, nullptr, Qhi, Qlo, 1);

    conv_act<<<MTOT * DM / 1024, 256>>>(k, Xhi, Xlo);
    tc_gemm<<<ggrid, 256, SMEM_GEMM>>>(Xhi, Xlo, WhT + 1 * DM * DM, WlT + 1 * DM * DM,
                                       nullptr, nullptr, Khi, Klo, 2);

    conv_act<<<MTOT * DM / 1024, 256>>>(v, Xhi, Xlo);
    tc_gemm<<<ggrid, 256, SMEM_GEMM>>>(Xhi, Xlo, WhT + 2 * DM * DM, WlT + 2 * DM * DM,
                                       bv, nullptr, Vhi, Vlo, 3);

    attn_tc<<<dim3(SEQ / 128, BATCH * NH), 256, SMEM_ATT>>>(Qhi, Qlo, Khi, Klo,
                                                            Vhi, Vlo, mask, At);

    conv_act<<<MTOT * DM / 1024, 256>>>(At, Xhi, Xlo);
    tc_gemm<<<ggrid, 256, SMEM_GEMM>>>(Xhi, Xlo, WhT + 3 * DM * DM, WlT + 3 * DM * DM,
                                       bf, out, nullptr, nullptr, 0);
}

// round 11
// speedup vs baseline: 2.5486x; 1.1467x over previous
#include <cuda_runtime.h>
#include <cuda_bf16.h>
#include <math.h>
#include <stdint.h>

// Problem constants
#define BATCH 2
#define SEQ   2048
#define DM    1024
#define NH    16
#define DK    64
#define MTOT  (BATCH*SEQ)       // 4096

// ---------------- scratch (no allocations allowed) ----------------
__device__ __nv_bfloat16 g_Xhi[MTOT*DM];
__device__ __nv_bfloat16 g_Xlo[MTOT*DM];
__device__ __nv_bfloat16 g_WhT[4][DM*DM];
__device__ __nv_bfloat16 g_WlT[4][DM*DM];
// attention operands (hi/lo bf16): Q,K: [bh][s][dk]; V: transposed [bh][dk][s]
__device__ __nv_bfloat16 g_Qhi[MTOT*DM];
__device__ __nv_bfloat16 g_Qlo[MTOT*DM];
__device__ __nv_bfloat16 g_Khi[MTOT*DM];
__device__ __nv_bfloat16 g_Klo[MTOT*DM];
__device__ __nv_bfloat16 g_Vhi[MTOT*DM];
__device__ __nv_bfloat16 g_Vlo[MTOT*DM];

__device__ __forceinline__ uint32_t smem_u32(const void* p) {
    uint32_t a;
    asm("{ .reg .u64 t; cvta.to.shared.u64 t, %1; cvt.u32.u64 %0, t; }"
        : "=r"(a) : "l"(p));
    return a;
}

#define CP16(dst_u32, src_ptr) \
    asm volatile("cp.async.ca.shared.global [%0], [%1], 16;" \
                 :: "r"(dst_u32), "l"((uint64_t)__cvta_generic_to_global(src_ptr)) : "memory")
#define CP_COMMIT() asm volatile("cp.async.commit_group;" ::: "memory")
#define CP_WAIT1()  asm volatile("cp.async.wait_group 1;" ::: "memory")
#define CP_WAIT0()  asm volatile("cp.async.wait_group 0;" ::: "memory")

#define LDSM4(r0, r1, r2, r3, addr) \
    asm volatile("ldmatrix.sync.aligned.m8n8.x4.shared.b16 {%0,%1,%2,%3}, [%4];" \
                 : "=r"(r0), "=r"(r1), "=r"(r2), "=r"(r3) : "r"(addr))

__device__ __forceinline__ void split2(float a, float b, uint32_t& hi, uint32_t& lo) {
    __nv_bfloat162 h = __float22bfloat162_rn(make_float2(a, b));
    float2 hf = __bfloat1622float2(h);
    __nv_bfloat162 l = __float22bfloat162_rn(make_float2(a - hf.x, b - hf.y));
    hi = *(uint32_t*)&h;
    lo = *(uint32_t*)&l;
}

__device__ __forceinline__ void mma16816(float* c, const uint32_t* a, const uint32_t* b) {
    asm volatile(
        "mma.sync.aligned.m16n8k16.row.col.f32.bf16.bf16.f32 "
        "{%0,%1,%2,%3},{%4,%5,%6,%7},{%8,%9},{%0,%1,%2,%3};"
        : "+f"(c[0]), "+f"(c[1]), "+f"(c[2]), "+f"(c[3])
        : "r"(a[0]), "r"(a[1]), "r"(a[2]), "r"(a[3]), "r"(b[0]), "r"(b[1]));
}

// ---------------- conversion pre-passes ----------------
__global__ __launch_bounds__(256)
void conv_act(const float* __restrict__ X,
              __nv_bfloat16* __restrict__ Xhi, __nv_bfloat16* __restrict__ Xlo)
{
    int idx = blockIdx.x * 256 + threadIdx.x;
    float4 x = ((const float4*)X)[idx];
    uint32_t h0, l0, h1, l1;
    split2(x.x, x.y, h0, l0);
    split2(x.z, x.w, h1, l1);
    ((uint2*)Xhi)[idx] = make_uint2(h0, h1);
    ((uint2*)Xlo)[idx] = make_uint2(l0, l1);
}

__global__ __launch_bounds__(256)
void conv_w(const float* __restrict__ W,
            __nv_bfloat16* __restrict__ WhT, __nv_bfloat16* __restrict__ WlT)
{
    __shared__ float ts[32][33];
    const int tx = threadIdx.x, ty = threadIdx.y;   // (32, 8)
    const int kt = blockIdx.y * 32, nt = blockIdx.x * 32;
#pragma unroll
    for (int i = 0; i < 4; i++)
        ts[ty + 8 * i][tx] = W[(size_t)(kt + ty + 8 * i) * DM + nt + tx];
    __syncthreads();
#pragma unroll
    for (int i = 0; i < 4; i++) {
        int n = nt + ty + 8 * i;
        int k = kt + tx;
        float v = ts[tx][ty + 8 * i];
        __nv_bfloat16 h = __float2bfloat16(v);
        __nv_bfloat16 l = __float2bfloat16(v - __bfloat162float(h));
        WhT[(size_t)n * DM + k] = h;
        WlT[(size_t)n * DM + k] = l;
    }
}

// ==================== HMMA bf16 GEMM ====================
// modes: 0 fp32 plain out; 1 Q->hi/lo bf16 [bh][s][dk] *0.125 (+bias);
//        2 K->hi/lo bf16 [bh][s][dk]; 3 V->hi/lo bf16 TRANSPOSED [bh][dk][s] (+bias)
#define ASTR  72
#define TILEB (128 * ASTR * 2)        // 18432 bytes per tile
#define STAGE (2 * TILEB)
#define SMEM_GEMM (2 * STAGE)         // 73728

__global__ __launch_bounds__(256)
void tc_gemm(const __nv_bfloat16* __restrict__ Xhi, const __nv_bfloat16* __restrict__ Xlo,
             const __nv_bfloat16* __restrict__ WhT, const __nv_bfloat16* __restrict__ WlT,
             const float* __restrict__ bias, float* __restrict__ Yf,
             __nv_bfloat16* __restrict__ Yh, __nv_bfloat16* __restrict__ Yl, int mode)
{
    extern __shared__ char sm[];
    const int tid  = threadIdx.x;
    const int wid  = tid >> 5;
    const int lane = tid & 31;
    const int wm   = wid >> 2;
    const int wn   = wid & 3;
    const int bm   = blockIdx.y * 128;
    const int bn   = blockIdx.x * 128;
    const uint32_t sb = smem_u32(sm);

    const int arow = tid >> 1;
    const int acol = (tid & 1) * 32;
    const uint32_t sdA = sb + (uint32_t)(arow * ASTR + acol) * 2;
    const uint32_t sdB = sdA + TILEB;

    // ldmatrix per-lane address offsets (halves) within a tile
    const int aoff0 = (wm * 64 + ((lane >> 3) & 1) * 8 + (lane & 7)) * ASTR + (lane >> 4) * 8;
    const int boff0 = (wn * 32 + ((lane >> 4)) * 8 + (lane & 7)) * ASTR + ((lane >> 3) & 1) * 8;

    float acc[4][4][4];
#pragma unroll
    for (int i = 0; i < 4; i++)
#pragma unroll
        for (int j = 0; j < 4; j++)
#pragma unroll
            for (int r = 0; r < 4; r++) acc[i][j][r] = 0.f;

    const __nv_bfloat16* Asrc0 = Xhi + (size_t)(bm + arow) * DM + acol;
    const __nv_bfloat16* Asrc2 = Xlo + (size_t)(bm + arow) * DM + acol;
    const __nv_bfloat16* Bsrc0 = WhT + (size_t)(bn + arow) * DM + acol;
    const __nv_bfloat16* Bsrc1 = WlT + (size_t)(bn + arow) * DM + acol;

    auto stage = [&](int buf, int it) {
        const int pass = it >> 4;
        const int k0   = (it & 15) * 64;
        const __nv_bfloat16* As = (pass == 2) ? Asrc2 : Asrc0;
        const __nv_bfloat16* Bs = (pass == 1) ? Bsrc1 : Bsrc0;
        const uint32_t dA = sdA + buf * STAGE;
        const uint32_t dB = sdB + buf * STAGE;
#pragma unroll
        for (int i = 0; i < 4; i++) {
            CP16(dA + i * 16, As + k0 + i * 8);
            CP16(dB + i * 16, Bs + k0 + i * 8);
        }
    };

    stage(0, 0);
    CP_COMMIT();

    const int r4 = lane >> 2;
    const int c4 = (lane & 3) * 2;

    for (int it = 0; it < 48; it++) {
        const int cur = it & 1;
        if (it + 1 < 48) stage(cur ^ 1, it + 1);
        CP_COMMIT();
        CP_WAIT1();
        __syncthreads();

        const uint32_t Abase = sb + cur * STAGE + aoff0 * 2;
        const uint32_t Bbase = sb + cur * STAGE + TILEB + boff0 * 2;

#pragma unroll
        for (int ks = 0; ks < 4; ks++) {
            uint32_t af[4][4], bf2[4][2];
#pragma unroll
            for (int mt = 0; mt < 4; mt++)
                LDSM4(af[mt][0], af[mt][1], af[mt][2], af[mt][3],
                      Abase + (uint32_t)(mt * 16 * ASTR + ks * 16) * 2);
#pragma unroll
            for (int np = 0; np < 2; np++)
                LDSM4(bf2[2 * np][0], bf2[2 * np][1], bf2[2 * np + 1][0], bf2[2 * np + 1][1],
                      Bbase + (uint32_t)(np * 16 * ASTR + ks * 16) * 2);
#pragma unroll
            for (int mt = 0; mt < 4; mt++)
#pragma unroll
                for (int nt = 0; nt < 4; nt++)
                    mma16816(acc[mt][nt], af[mt], bf2[nt]);
        }
        __syncthreads();
    }

    // ---------------- epilogue ----------------
#pragma unroll
    for (int mt = 0; mt < 4; mt++) {
#pragma unroll
        for (int rr = 0; rr < 2; rr++) {
            const int m  = bm + wm * 64 + mt * 16 + r4 + rr * 8;
            const int bq = m >> 11, sq = m & (SEQ - 1);
#pragma unroll
            for (int nt = 0; nt < 4; nt++) {
                const int n = bn + wn * 32 + nt * 8 + c4;
                float v0 = acc[mt][nt][rr * 2], v1 = acc[mt][nt][rr * 2 + 1];
                if (bias) { v0 += bias[n]; v1 += bias[n + 1]; }
                if (mode == 1) { v0 *= 0.125f; v1 *= 0.125f; }
                if (mode == 0) {
                    *(float2*)&Yf[(size_t)m * DM + n] = make_float2(v0, v1);
                } else if (mode == 3) {
                    const int hh = n >> 6, dk = n & 63;
                    size_t i0 = ((size_t)(bq * NH + hh) * DK + dk) * SEQ + sq;
                    __nv_bfloat16 h0 = __float2bfloat16(v0);
                    __nv_bfloat16 h1 = __float2bfloat16(v1);
                    Yh[i0]       = h0;
                    Yh[i0 + SEQ] = h1;
                    Yl[i0]       = __float2bfloat16(v0 - __bfloat162float(h0));
                    Yl[i0 + SEQ] = __float2bfloat16(v1 - __bfloat162float(h1));
                } else {
                    uint32_t hi, lo;
                    split2(v0, v1, hi, lo);
                    const int hh = n >> 6, dk = n & 63;
                    size_t idx = ((size_t)(bq * NH + hh) * SEQ + sq) * DK + dk;
                    *(uint32_t*)&Yh[idx] = hi;
                    *(uint32_t*)&Yl[idx] = lo;
                }
            }
        }
    }
}

// ==================== HMMA flash attention ====================
// grid (16, 32): Q tile 128 rows, 8 warps x 16 rows. K-tiles of 64, 32 iters.
// Output written directly as hi/lo bf16 [b*s][h*dk] (input of final GEMM).
#define ATSTR 72
#define ATILE (64 * ATSTR * 2)    // 9216 B
#define ASTAGE (4 * ATILE)        // 36864: Khi, Klo, Vhi, Vlo
#define QTILE (128 * ATSTR * 2)   // 18432
#define SMEM_ATT (2 * ASTAGE)     // 73728

__global__ __launch_bounds__(256)
void attn_tc(const __nv_bfloat16* __restrict__ Qhi_, const __nv_bfloat16* __restrict__ Qlo_,
             const __nv_bfloat16* __restrict__ Khi_, const __nv_bfloat16* __restrict__ Klo_,
             const __nv_bfloat16* __restrict__ Vhi_, const __nv_bfloat16* __restrict__ Vlo_,
             const int* __restrict__ mask,
             __nv_bfloat16* __restrict__ Ohi, __nv_bfloat16* __restrict__ Olo)
{
    extern __shared__ char sm[];
    const int tid  = threadIdx.x;
    const int wid  = tid >> 5;
    const int lane = tid & 31;
    const int r4   = lane >> 2;
    const int c4   = (lane & 3) * 2;
    const int qt   = blockIdx.x;
    const int bh   = blockIdx.y;
    const int b    = bh >> 4;
    const int h    = bh & 15;
    const uint32_t sb = smem_u32(sm);

    // ---- stage Q hi/lo (128x64), load frags to registers ----
#pragma unroll
    for (int i = 0; i < 4; i++) {
        int c   = tid + i * 256;
        int row = c >> 3;
        int off = (c & 7) * 8;
        const __nv_bfloat16* s0 = Qhi_ + ((size_t)bh * SEQ + qt * 128 + row) * DK + off;
        const __nv_bfloat16* s1 = Qlo_ + ((size_t)bh * SEQ + qt * 128 + row) * DK + off;
        uint32_t d = sb + (uint32_t)(row * ATSTR + off) * 2;
        CP16(d, s0);
        CP16(d + QTILE, s1);
    }
    CP_COMMIT();
    CP_WAIT0();
    __syncthreads();

    // Q frag addresses via ldmatrix (tile rows = wid*16..)
    uint32_t qh[4][4], ql[4][4];
    {
        const uint32_t qoff = (uint32_t)((wid * 16 + ((lane >> 3) & 1) * 8 + (lane & 7)) * ATSTR
                                          + (lane >> 4) * 8) * 2;
#pragma unroll
        for (int ks = 0; ks < 4; ks++) {
            LDSM4(qh[ks][0], qh[ks][1], qh[ks][2], qh[ks][3], sb + qoff + ks * 32);
            LDSM4(ql[ks][0], ql[ks][1], ql[ks][2], ql[ks][3], sb + QTILE + qoff + ks * 32);
        }
    }
    __syncthreads();   // Q area reused for K/V staging

    auto stageKV = [&](int buf, int kt) {
        const int row = tid >> 2;              // 0..63
        const int off = ((tid & 3) * 2) * 8;   // halves: 0,16,32,48
        uint32_t d = sb + buf * ASTAGE + (uint32_t)(row * ATSTR + off) * 2;
        const __nv_bfloat16* k0 = Khi_ + ((size_t)bh * SEQ + kt * 64 + row) * DK + off;
        const __nv_bfloat16* k1 = Klo_ + ((size_t)bh * SEQ + kt * 64 + row) * DK + off;
        const __nv_bfloat16* v0 = Vhi_ + ((size_t)bh * DK + row) * SEQ + kt * 64 + off;
        const __nv_bfloat16* v1 = Vlo_ + ((size_t)bh * DK + row) * SEQ + kt * 64 + off;
        CP16(d,                  k0);     CP16(d + 16,              k0 + 8);
        CP16(d + ATILE,          k1);     CP16(d + ATILE + 16,      k1 + 8);
        CP16(d + 2 * ATILE,      v0);     CP16(d + 2 * ATILE + 16,  v0 + 8);
        CP16(d + 3 * ATILE,      v1);     CP16(d + 3 * ATILE + 16,  v1 + 8);
    };

    stageKV(0, 0);
    CP_COMMIT();

    float oacc[8][4];
#pragma unroll
    for (int nb = 0; nb < 8; nb++)
#pragma unroll
        for (int r = 0; r < 4; r++) oacc[nb][r] = 0.f;
    float mrun0 = -1e30f, mrun1 = -1e30f, lrun0 = 0.f, lrun1 = 0.f;

    const int ro0 = qt * 128 + wid * 16 + r4;
    const int* mrow = mask + ((size_t)b * SEQ + ro0) * SEQ;

    // ldmatrix lane offset within a K/V tile (rows = n/dv)
    const uint32_t kvoff = (uint32_t)(((lane >> 4) * 8 + (lane & 7)) * ATSTR
                                       + ((lane >> 3) & 1) * 8) * 2;

    for (int kt = 0; kt < 32; kt++) {
        const int cur = kt & 1;
        if (kt + 1 < 32) { stageKV(cur ^ 1, kt + 1); CP_COMMIT(); CP_WAIT1(); }
        else             { CP_WAIT0(); }
        __syncthreads();

        const uint32_t KhB = sb + cur * ASTAGE + kvoff;
        const uint32_t KlB = KhB + ATILE;
        const uint32_t VhB = KhB + 2 * ATILE;
        const uint32_t VlB = KhB + 3 * ATILE;

        // ---- scores: S = Q K^T (3-pass) ----
        float sacc[8][4];
#pragma unroll
        for (int nb = 0; nb < 8; nb++)
#pragma unroll
            for (int r = 0; r < 4; r++) sacc[nb][r] = 0.f;

#pragma unroll
        for (int ks = 0; ks < 4; ks++) {
            uint32_t kh2[8][2], kl2[8][2];
#pragma unroll
            for (int np = 0; np < 4; np++) {
                const uint32_t o = (uint32_t)(np * 16 * ATSTR) * 2 + ks * 32;
                LDSM4(kh2[2 * np][0], kh2[2 * np][1], kh2[2 * np + 1][0], kh2[2 * np + 1][1],
                      KhB + o);
                LDSM4(kl2[2 * np][0], kl2[2 * np][1], kl2[2 * np + 1][0], kl2[2 * np + 1][1],
                      KlB + o);
            }
#pragma unroll
            for (int nb = 0; nb < 8; nb++) mma16816(sacc[nb], qh[ks], kh2[nb]);
#pragma unroll
            for (int nb = 0; nb < 8; nb++) mma16816(sacc[nb], qh[ks], kl2[nb]);
#pragma unroll
            for (int nb = 0; nb < 8; nb++) mma16816(sacc[nb], ql[ks], kh2[nb]);
        }

        // ---- mask ----
        const int* mc = mrow + kt * 64;
#pragma unroll
        for (int nb = 0; nb < 8; nb++) {
            int2 mv0 = *(const int2*)(mc + nb * 8 + c4);
            int2 mv1 = *(const int2*)(mc + 8 * SEQ + nb * 8 + c4);
            if (mv0.x == 0) sacc[nb][0] = -1e30f;
            if (mv0.y == 0) sacc[nb][1] = -1e30f;
            if (mv1.x == 0) sacc[nb][2] = -1e30f;
            if (mv1.y == 0) sacc[nb][3] = -1e30f;
        }

        // ---- online softmax ----
        float mx0 = -1e30f, mx1 = -1e30f;
#pragma unroll
        for (int nb = 0; nb < 8; nb++) {
            mx0 = fmaxf(mx0, fmaxf(sacc[nb][0], sacc[nb][1]));
            mx1 = fmaxf(mx1, fmaxf(sacc[nb][2], sacc[nb][3]));
        }
        mx0 = fmaxf(mx0, __shfl_xor_sync(0xffffffffu, mx0, 1));
        mx0 = fmaxf(mx0, __shfl_xor_sync(0xffffffffu, mx0, 2));
        mx1 = fmaxf(mx1, __shfl_xor_sync(0xffffffffu, mx1, 1));
        mx1 = fmaxf(mx1, __shfl_xor_sync(0xffffffffu, mx1, 2));

        const float mn0 = fmaxf(mrun0, mx0);
        const float mn1 = fmaxf(mrun1, mx1);
        const float scl0 = __expf(mrun0 - mn0);
        const float scl1 = __expf(mrun1 - mn1);
        mrun0 = mn0; mrun1 = mn1;

        float rs0 = 0.f, rs1 = 0.f;
#pragma unroll
        for (int nb = 0; nb < 8; nb++) {
            sacc[nb][0] = __expf(sacc[nb][0] - mn0);
            sacc[nb][1] = __expf(sacc[nb][1] - mn0);
            sacc[nb][2] = __expf(sacc[nb][2] - mn1);
            sacc[nb][3] = __expf(sacc[nb][3] - mn1);
            rs0 += sacc[nb][0] + sacc[nb][1];
            rs1 += sacc[nb][2] + sacc[nb][3];
        }
        rs0 += __shfl_xor_sync(0xffffffffu, rs0, 1);
        rs0 += __shfl_xor_sync(0xffffffffu, rs0, 2);
        rs1 += __shfl_xor_sync(0xffffffffu, rs1, 1);
        rs1 += __shfl_xor_sync(0xffffffffu, rs1, 2);
        lrun0 = lrun0 * scl0 + rs0;
        lrun1 = lrun1 * scl1 + rs1;

#pragma unroll
        for (int nb = 0; nb < 8; nb++) {
            oacc[nb][0] *= scl0; oacc[nb][1] *= scl0;
            oacc[nb][2] *= scl1; oacc[nb][3] *= scl1;
        }

        // ---- P -> hi/lo A-fragments ----
        uint32_t pah[4][4], pal[4][4];
#pragma unroll
        for (int ks = 0; ks < 4; ks++) {
            split2(sacc[2 * ks][0],     sacc[2 * ks][1],     pah[ks][0], pal[ks][0]);
            split2(sacc[2 * ks][2],     sacc[2 * ks][3],     pah[ks][1], pal[ks][1]);
            split2(sacc[2 * ks + 1][0], sacc[2 * ks + 1][1], pah[ks][2], pal[ks][2]);
            split2(sacc[2 * ks + 1][2], sacc[2 * ks + 1][3], pah[ks][3], pal[ks][3]);
        }

        // ---- O += P V (3-pass) ----
#pragma unroll
        for (int ks = 0; ks < 4; ks++) {
            uint32_t vh2[8][2], vl2[8][2];
#pragma unroll
            for (int np = 0; np < 4; np++) {
                const uint32_t o = (uint32_t)(np * 16 * ATSTR) * 2 + ks * 32;
                LDSM4(vh2[2 * np][0], vh2[2 * np][1], vh2[2 * np + 1][0], vh2[2 * np + 1][1],
                      VhB + o);
                LDSM4(vl2[2 * np][0], vl2[2 * np][1], vl2[2 * np + 1][0], vl2[2 * np + 1][1],
                      VlB + o);
            }
#pragma unroll
            for (int nb = 0; nb < 8; nb++) mma16816(oacc[nb], pah[ks], vh2[nb]);
#pragma unroll
            for (int nb = 0; nb < 8; nb++) mma16816(oacc[nb], pah[ks], vl2[nb]);
#pragma unroll
            for (int nb = 0; nb < 8; nb++) mma16816(oacc[nb], pal[ks], vh2[nb]);
        }
        __syncthreads();
    }

    // ---- epilogue: normalize, emit hi/lo bf16 [b*s][h*dk] ----
    const float inv0 = (lrun0 > 0.f) ? 1.f / lrun0 : 0.f;
    const float inv1 = (lrun1 > 0.f) ? 1.f / lrun1 : 0.f;
    const size_t m0 = (size_t)b * SEQ + ro0;
#pragma unroll
    for (int nb = 0; nb < 8; nb++) {
        const int col = h * DK + nb * 8 + c4;
        uint32_t hi, lo;
        split2(oacc[nb][0] * inv0, oacc[nb][1] * inv0, hi, lo);
        *(uint32_t*)&Ohi[m0 * DM + col] = hi;
        *(uint32_t*)&Olo[m0 * DM + col] = lo;
        split2(oacc[nb][2] * inv1, oacc[nb][3] * inv1, hi, lo);
        *(uint32_t*)&Ohi[(m0 + 8) * DM + col] = hi;
        *(uint32_t*)&Olo[(m0 + 8) * DM + col] = lo;
    }
}

// ---------------- launch ----------------
extern "C" void kernel_launch(void* const* d_in, const int* in_sizes, int n_in,
                              void* d_out, int out_size)
{
    const float* q    = (const float*)d_in[0];
    const float* k    = (const float*)d_in[1];
    const float* v    = (const float*)d_in[2];
    const int*   mask = (const int*)  d_in[3];
    const float* wq   = (const float*)d_in[4];
    const float* bq   = (const float*)d_in[5];
    const float* wk   = (const float*)d_in[6];
    const float* wv   = (const float*)d_in[7];
    const float* bv   = (const float*)d_in[8];
    const float* wf   = (const float*)d_in[9];
    const float* bf   = (const float*)d_in[10];
    float* out = (float*)d_out;

    __nv_bfloat16 *Xhi, *Xlo, *WhT, *WlT, *Qhi, *Qlo, *Khi, *Klo, *Vhi, *Vlo;
    cudaGetSymbolAddress((void**)&Xhi, g_Xhi);
    cudaGetSymbolAddress((void**)&Xlo, g_Xlo);
    cudaGetSymbolAddress((void**)&WhT, g_WhT);
    cudaGetSymbolAddress((void**)&WlT, g_WlT);
    cudaGetSymbolAddress((void**)&Qhi, g_Qhi);
    cudaGetSymbolAddress((void**)&Qlo, g_Qlo);
    cudaGetSymbolAddress((void**)&Khi, g_Khi);
    cudaGetSymbolAddress((void**)&Klo, g_Klo);
    cudaGetSymbolAddress((void**)&Vhi, g_Vhi);
    cudaGetSymbolAddress((void**)&Vlo, g_Vlo);

    cudaFuncSetAttribute(tc_gemm,
                         cudaFuncAttributeMaxDynamicSharedMemorySize, SMEM_GEMM);
    cudaFuncSetAttribute(attn_tc,
                         cudaFuncAttributeMaxDynamicSharedMemorySize, SMEM_ATT);

    dim3 wgrid(32, 32);
    dim3 wblk(32, 8);
    conv_w<<<wgrid, wblk>>>(wq, WhT + 0 * DM * DM, WlT + 0 * DM * DM);
    conv_w<<<wgrid, wblk>>>(wk, WhT + 1 * DM * DM, WlT + 1 * DM * DM);
    conv_w<<<wgrid, wblk>>>(wv, WhT + 2 * DM * DM, WlT + 2 * DM * DM);
    conv_w<<<wgrid, wblk>>>(wf, WhT + 3 * DM * DM, WlT + 3 * DM * DM);

    dim3 ggrid(DM / 128, MTOT / 128);   // (8, 32)

    conv_act<<<MTOT * DM / 1024, 256>>>(q, Xhi, Xlo);
    tc_gemm<<<ggrid, 256, SMEM_GEMM>>>(Xhi, Xlo, WhT + 0 * DM * DM, WlT + 0 * DM * DM,
                                       bq, nullptr, Qhi, Qlo, 1);

    conv_act<<<MTOT * DM / 1024, 256>>>(k, Xhi, Xlo);
    tc_gemm<<<ggrid, 256, SMEM_GEMM>>>(Xhi, Xlo, WhT + 1 * DM * DM, WlT + 1 * DM * DM,
                                       nullptr, nullptr, Khi, Klo, 2);

    conv_act<<<MTOT * DM / 1024, 256>>>(v, Xhi, Xlo);
    tc_gemm<<<ggrid, 256, SMEM_GEMM>>>(Xhi, Xlo, WhT + 2 * DM * DM, WlT + 2 * DM * DM,
                                       bv, nullptr, Vhi, Vlo, 3);

    // attention writes hi/lo bf16 directly into the final GEMM's input buffers
    attn_tc<<<dim3(SEQ / 128, BATCH * NH), 256, SMEM_ATT>>>(Qhi, Qlo, Khi, Klo,
                                                            Vhi, Vlo, mask, Xhi, Xlo);

    tc_gemm<<<ggrid, 256, SMEM_GEMM>>>(Xhi, Xlo, WhT + 3 * DM * DM, WlT + 3 * DM * DM,
                                       bf, out, nullptr, nullptr, 0);
}

// round 13
// speedup vs baseline: 3.0087x; 1.1805x over previous
#include <cuda_runtime.h>
#include <cuda_bf16.h>
#include <math.h>
#include <stdint.h>

// Problem constants
#define BATCH 2
#define SEQ   2048
#define DM    1024
#define NH    16
#define DK    64
#define MTOT  (BATCH*SEQ)       // 4096

// ---------------- scratch (no allocations allowed) ----------------
__device__ __nv_bfloat16 g_Xhi[MTOT*DM];
__device__ __nv_bfloat16 g_Xlo[MTOT*DM];
__device__ __nv_bfloat16 g_WhT[4][DM*DM];
__device__ __nv_bfloat16 g_WlT[4][DM*DM];
__device__ __nv_bfloat16 g_Qhi[MTOT*DM];
__device__ __nv_bfloat16 g_Qlo[MTOT*DM];
__device__ __nv_bfloat16 g_Khi[MTOT*DM];
__device__ __nv_bfloat16 g_Klo[MTOT*DM];
__device__ __nv_bfloat16 g_Vhi[MTOT*DM];
__device__ __nv_bfloat16 g_Vlo[MTOT*DM];
__device__ uint64_t      g_Mpk[BATCH*SEQ*(SEQ/64)];   // bit-packed mask, 1MB

__device__ __forceinline__ uint32_t smem_u32(const void* p) {
    uint32_t a;
    asm("{ .reg .u64 t; cvta.to.shared.u64 t, %1; cvt.u32.u64 %0, t; }"
        : "=r"(a) : "l"(p));
    return a;
}

#define CP16(dst_u32, src_ptr) \
    asm volatile("cp.async.ca.shared.global [%0], [%1], 16;" \
                 :: "r"(dst_u32), "l"((uint64_t)__cvta_generic_to_global(src_ptr)) : "memory")
#define CP_COMMIT() asm volatile("cp.async.commit_group;" ::: "memory")
#define CP_WAIT2()  asm volatile("cp.async.wait_group 2;" ::: "memory")
#define CP_WAIT1()  asm volatile("cp.async.wait_group 1;" ::: "memory")
#define CP_WAIT0()  asm volatile("cp.async.wait_group 0;" ::: "memory")

#define LDSM4(r0, r1, r2, r3, addr) \
    asm volatile("ldmatrix.sync.aligned.m8n8.x4.shared.b16 {%0,%1,%2,%3}, [%4];" \
                 : "=r"(r0), "=r"(r1), "=r"(r2), "=r"(r3) : "r"(addr))

__device__ __forceinline__ void split2(float a, float b, uint32_t& hi, uint32_t& lo) {
    __nv_bfloat162 h = __float22bfloat162_rn(make_float2(a, b));
    float2 hf = __bfloat1622float2(h);
    __nv_bfloat162 l = __float22bfloat162_rn(make_float2(a - hf.x, b - hf.y));
    hi = *(uint32_t*)&h;
    lo = *(uint32_t*)&l;
}

__device__ __forceinline__ void mma16816(float* c, const uint32_t* a, const uint32_t* b) {
    asm volatile(
        "mma.sync.aligned.m16n8k16.row.col.f32.bf16.bf16.f32 "
        "{%0,%1,%2,%3},{%4,%5,%6,%7},{%8,%9},{%0,%1,%2,%3};"
        : "+f"(c[0]), "+f"(c[1]), "+f"(c[2]), "+f"(c[3])
        : "r"(a[0]), "r"(a[1]), "r"(a[2]), "r"(a[3]), "r"(b[0]), "r"(b[1]));
}

// ---------------- pre-passes ----------------
__global__ __launch_bounds__(256)
void conv_act(const float* __restrict__ X,
              __nv_bfloat16* __restrict__ Xhi, __nv_bfloat16* __restrict__ Xlo)
{
    int idx = blockIdx.x * 256 + threadIdx.x;
    float4 x = ((const float4*)X)[idx];
    uint32_t h0, l0, h1, l1;
    split2(x.x, x.y, h0, l0);
    split2(x.z, x.w, h1, l1);
    ((uint2*)Xhi)[idx] = make_uint2(h0, h1);
    ((uint2*)Xlo)[idx] = make_uint2(l0, l1);
}

__global__ __launch_bounds__(256)
void conv_w(const float* __restrict__ W,
            __nv_bfloat16* __restrict__ WhT, __nv_bfloat16* __restrict__ WlT)
{
    __shared__ float ts[32][33];
    const int tx = threadIdx.x, ty = threadIdx.y;   // (32, 8)
    const int kt = blockIdx.y * 32, nt = blockIdx.x * 32;
#pragma unroll
    for (int i = 0; i < 4; i++)
        ts[ty + 8 * i][tx] = W[(size_t)(kt + ty + 8 * i) * DM + nt + tx];
    __syncthreads();
#pragma unroll
    for (int i = 0; i < 4; i++) {
        int n = nt + ty + 8 * i;
        int k = kt + tx;
        float v = ts[tx][ty + 8 * i];
        __nv_bfloat16 h = __float2bfloat16(v);
        __nv_bfloat16 l = __float2bfloat16(v - __bfloat162float(h));
        WhT[(size_t)n * DM + k] = h;
        WlT[(size_t)n * DM + k] = l;
    }
}

// pack mask: 64 int32 -> 1 uint64 (bit j = mask[col j] != 0)
__global__ __launch_bounds__(256)
void pack_mask(const int* __restrict__ mask, uint64_t* __restrict__ Mpk)
{
    int idx = blockIdx.x * 256 + threadIdx.x;   // word index, 131072 total
    const int4* src = (const int4*)mask + (size_t)idx * 16;
    uint64_t w = 0;
#pragma unroll
    for (int i = 0; i < 16; i++) {
        int4 v = src[i];
        uint64_t nib = (uint64_t)((v.x != 0) | ((v.y != 0) << 1) |
                                  ((v.z != 0) << 2) | ((v.w != 0) << 3));
        w |= nib << (i * 4);
    }
    Mpk[idx] = w;
}

// ==================== HMMA bf16 GEMM (pass-fused) ====================
// modes: 0 fp32 plain out; 1 Q->hi/lo bf16 [bh][s][dk] *0.125 (+bias);
//        2 K->hi/lo bf16 [bh][s][dk]; 3 V->hi/lo bf16 TRANSPOSED [bh][dk][s] (+bias)
#define BSTR  40
#define T2B   (128 * BSTR * 2)     // 10240 bytes per tile (128 x 32 halves)
#define STG2  (4 * T2B)            // 40960: Ahi, Alo, Bhi, Blo
#define SMEM_GEMM (2 * STG2)       // 81920

__global__ __launch_bounds__(256)
void tc_gemm(const __nv_bfloat16* __restrict__ Xhi, const __nv_bfloat16* __restrict__ Xlo,
             const __nv_bfloat16* __restrict__ WhT, const __nv_bfloat16* __restrict__ WlT,
             const float* __restrict__ bias, float* __restrict__ Yf,
             __nv_bfloat16* __restrict__ Yh, __nv_bfloat16* __restrict__ Yl, int mode)
{
    extern __shared__ char sm[];
    const int tid  = threadIdx.x;
    const int wid  = tid >> 5;
    const int lane = tid & 31;
    const int wm   = wid >> 2;
    const int wn   = wid & 3;
    const int bm   = blockIdx.y * 128;
    const int bn   = blockIdx.x * 128;
    const uint32_t sb = smem_u32(sm);

    // staging: row = tid>>1 (0..127), colh = (tid&1)*16 halves (32 cols per block)
    const int row  = tid >> 1;
    const int colh = (tid & 1) * 16;
    const uint32_t sd = sb + (uint32_t)(row * BSTR + colh) * 2;

    const __nv_bfloat16* Ah_src = Xhi + (size_t)(bm + row) * DM + colh;
    const __nv_bfloat16* Al_src = Xlo + (size_t)(bm + row) * DM + colh;
    const __nv_bfloat16* Bh_src = WhT + (size_t)(bn + row) * DM + colh;
    const __nv_bfloat16* Bl_src = WlT + (size_t)(bn + row) * DM + colh;

    auto stage = [&](int buf, int blk) {
        const int k0 = blk * 32;
        const uint32_t d = sd + buf * STG2;
        CP16(d,                Ah_src + k0);  CP16(d + 16,           Ah_src + k0 + 8);
        CP16(d + T2B,          Al_src + k0);  CP16(d + T2B + 16,     Al_src + k0 + 8);
        CP16(d + 2 * T2B,      Bh_src + k0);  CP16(d + 2 * T2B + 16, Bh_src + k0 + 8);
        CP16(d + 3 * T2B,      Bl_src + k0);  CP16(d + 3 * T2B + 16, Bl_src + k0 + 8);
    };

    // ldmatrix per-lane offsets (halves) within a tile
    const int aoff0 = (wm * 64 + ((lane >> 3) & 1) * 8 + (lane & 7)) * BSTR + (lane >> 4) * 8;
    const int boff0 = (wn * 32 + ((lane >> 4)) * 8 + (lane & 7)) * BSTR + ((lane >> 3) & 1) * 8;

    float acc[4][4][4];
#pragma unroll
    for (int i = 0; i < 4; i++)
#pragma unroll
        for (int j = 0; j < 4; j++)
#pragma unroll
            for (int r = 0; r < 4; r++) acc[i][j][r] = 0.f;

    stage(0, 0);
    CP_COMMIT();

    const int r4 = lane >> 2;
    const int c4 = (lane & 3) * 2;

    for (int it = 0; it < 32; it++) {
        const int cur = it & 1;
        if (it + 1 < 32) stage(cur ^ 1, it + 1);
        CP_COMMIT();
        CP_WAIT1();
        __syncthreads();

        const uint32_t AhB = sb + cur * STG2 + aoff0 * 2;
        const uint32_t AlB = AhB + T2B;
        const uint32_t BhB = sb + cur * STG2 + 2 * T2B + boff0 * 2;
        const uint32_t BlB = BhB + T2B;

#pragma unroll
        for (int ks = 0; ks < 2; ks++) {
            const uint32_t ko = (uint32_t)(ks * 16) * 2;
            uint32_t ah[4][4], al[4][4], bh[4][2], bl[4][2];
#pragma unroll
            for (int mt = 0; mt < 4; mt++) {
                const uint32_t mo = (uint32_t)(mt * 16 * BSTR) * 2 + ko;
                LDSM4(ah[mt][0], ah[mt][1], ah[mt][2], ah[mt][3], AhB + mo);
                LDSM4(al[mt][0], al[mt][1], al[mt][2], al[mt][3], AlB + mo);
            }
#pragma unroll
            for (int np = 0; np < 2; np++)
                LDSM4(bh[2 * np][0], bh[2 * np][1], bh[2 * np + 1][0], bh[2 * np + 1][1],
                      BhB + (uint32_t)(np * 16 * BSTR) * 2 + ko);
#pragma unroll
            for (int mt = 0; mt < 4; mt++)
#pragma unroll
                for (int nt = 0; nt < 4; nt++)
                    mma16816(acc[mt][nt], ah[mt], bh[nt]);
#pragma unroll
            for (int mt = 0; mt < 4; mt++)
#pragma unroll
                for (int nt = 0; nt < 4; nt++)
                    mma16816(acc[mt][nt], al[mt], bh[nt]);
#pragma unroll
            for (int np = 0; np < 2; np++)
                LDSM4(bl[2 * np][0], bl[2 * np][1], bl[2 * np + 1][0], bl[2 * np + 1][1],
                      BlB + (uint32_t)(np * 16 * BSTR) * 2 + ko);
#pragma unroll
            for (int mt = 0; mt < 4; mt++)
#pragma unroll
                for (int nt = 0; nt < 4; nt++)
                    mma16816(acc[mt][nt], ah[mt], bl[nt]);
        }
        __syncthreads();
    }

    // ---------------- epilogue ----------------
#pragma unroll
    for (int mt = 0; mt < 4; mt++) {
#pragma unroll
        for (int rr = 0; rr < 2; rr++) {
            const int m  = bm + wm * 64 + mt * 16 + r4 + rr * 8;
            const int bq = m >> 11, sq = m & (SEQ - 1);
#pragma unroll
            for (int nt = 0; nt < 4; nt++) {
                const int n = bn + wn * 32 + nt * 8 + c4;
                float v0 = acc[mt][nt][rr * 2], v1 = acc[mt][nt][rr * 2 + 1];
                if (bias) { v0 += bias[n]; v1 += bias[n + 1]; }
                if (mode == 1) { v0 *= 0.125f; v1 *= 0.125f; }
                if (mode == 0) {
                    *(float2*)&Yf[(size_t)m * DM + n] = make_float2(v0, v1);
                } else if (mode == 3) {
                    const int hh = n >> 6, dk = n & 63;
                    size_t i0 = ((size_t)(bq * NH + hh) * DK + dk) * SEQ + sq;
                    __nv_bfloat16 h0 = __float2bfloat16(v0);
                    __nv_bfloat16 h1 = __float2bfloat16(v1);
                    Yh[i0]       = h0;
                    Yh[i0 + SEQ] = h1;
                    Yl[i0]       = __float2bfloat16(v0 - __bfloat162float(h0));
                    Yl[i0 + SEQ] = __float2bfloat16(v1 - __bfloat162float(h1));
                } else {
                    uint32_t hi, lo;
                    split2(v0, v1, hi, lo);
                    const int hh = n >> 6, dk = n & 63;
                    size_t idx = ((size_t)(bq * NH + hh) * SEQ + sq) * DK + dk;
                    *(uint32_t*)&Yh[idx] = hi;
                    *(uint32_t*)&Yl[idx] = lo;
                }
            }
        }
    }
}

// ==================== HMMA flash attention ====================
// grid (16, 32): Q tile 128 rows, 8 warps x 16 rows. K-tiles of 64, 32 iters.
// 3-stage cp.async KV pipeline; bit-packed mask; output hi/lo bf16 [b*s][h*dk].
#define ATSTR 72
#define ATILE (64 * ATSTR * 2)    // 9216 B
#define ASTAGE (4 * ATILE)        // 36864: Khi, Klo, Vhi, Vlo
#define QTILE (128 * ATSTR * 2)   // 18432
#define SMEM_ATT (3 * ASTAGE)     // 110592

__global__ __launch_bounds__(256)
void attn_tc(const __nv_bfloat16* __restrict__ Qhi_, const __nv_bfloat16* __restrict__ Qlo_,
             const __nv_bfloat16* __restrict__ Khi_, const __nv_bfloat16* __restrict__ Klo_,
             const __nv_bfloat16* __restrict__ Vhi_, const __nv_bfloat16* __restrict__ Vlo_,
             const uint64_t* __restrict__ Mpk,
             __nv_bfloat16* __restrict__ Ohi, __nv_bfloat16* __restrict__ Olo)
{
    extern __shared__ char sm[];
    const int tid  = threadIdx.x;
    const int wid  = tid >> 5;
    const int lane = tid & 31;
    const int r4   = lane >> 2;
    const int c4   = (lane & 3) * 2;
    const int qt   = blockIdx.x;
    const int bh   = blockIdx.y;
    const int b    = bh >> 4;
    const int h    = bh & 15;
    const uint32_t sb = smem_u32(sm);

    // ---- stage Q hi/lo (128x64) into stage-0 area, load frags to registers ----
#pragma unroll
    for (int i = 0; i < 4; i++) {
        int c   = tid + i * 256;
        int qrow = c >> 3;
        int off = (c & 7) * 8;
        const __nv_bfloat16* s0 = Qhi_ + ((size_t)bh * SEQ + qt * 128 + qrow) * DK + off;
        const __nv_bfloat16* s1 = Qlo_ + ((size_t)bh * SEQ + qt * 128 + qrow) * DK + off;
        uint32_t d = sb + (uint32_t)(qrow * ATSTR + off) * 2;
        CP16(d, s0);
        CP16(d + QTILE, s1);
    }
    CP_COMMIT();
    CP_WAIT0();
    __syncthreads();

    uint32_t qh[4][4], ql[4][4];
    {
        const uint32_t qoff = (uint32_t)((wid * 16 + ((lane >> 3) & 1) * 8 + (lane & 7)) * ATSTR
                                          + (lane >> 4) * 8) * 2;
#pragma unroll
        for (int ks = 0; ks < 4; ks++) {
            LDSM4(qh[ks][0], qh[ks][1], qh[ks][2], qh[ks][3], sb + qoff + ks * 32);
            LDSM4(ql[ks][0], ql[ks][1], ql[ks][2], ql[ks][3], sb + QTILE + qoff + ks * 32);
        }
    }
    __syncthreads();   // Q area reused for KV stage 0

    auto stageKV = [&](int buf, int kt) {
        const int krow = tid >> 2;             // 0..63
        const int off  = (tid & 3) * 16;       // halves
        uint32_t d = sb + buf * ASTAGE + (uint32_t)(krow * ATSTR + off) * 2;
        const __nv_bfloat16* k0 = Khi_ + ((size_t)bh * SEQ + kt * 64 + krow) * DK + off;
        const __nv_bfloat16* k1 = Klo_ + ((size_t)bh * SEQ + kt * 64 + krow) * DK + off;
        const __nv_bfloat16* v0 = Vhi_ + ((size_t)bh * DK + krow) * SEQ + kt * 64 + off;
        const __nv_bfloat16* v1 = Vlo_ + ((size_t)bh * DK + krow) * SEQ + kt * 64 + off;
        CP16(d,                  k0);     CP16(d + 16,              k0 + 8);
        CP16(d + ATILE,          k1);     CP16(d + ATILE + 16,      k1 + 8);
        CP16(d + 2 * ATILE,      v0);     CP16(d + 2 * ATILE + 16,  v0 + 8);
        CP16(d + 3 * ATILE,      v1);     CP16(d + 3 * ATILE + 16,  v1 + 8);
    };

    stageKV(0, 0); CP_COMMIT();
    stageKV(1, 1); CP_COMMIT();

    float oacc[8][4];
#pragma unroll
    for (int nb = 0; nb < 8; nb++)
#pragma unroll
        for (int r = 0; r < 4; r++) oacc[nb][r] = 0.f;
    float mrun0 = -1e30f, mrun1 = -1e30f, lrun0 = 0.f, lrun1 = 0.f;

    const int ro0 = qt * 128 + wid * 16 + r4;
    const uint64_t* mrow0 = Mpk + ((size_t)b * SEQ + ro0) * (SEQ / 64);
    const uint64_t* mrow1 = mrow0 + 8 * (SEQ / 64);

    const uint32_t kvoff = (uint32_t)(((lane >> 4) * 8 + (lane & 7)) * ATSTR
                                       + ((lane >> 3) & 1) * 8) * 2;

    int cur = 0;
    for (int kt = 0; kt < 32; kt++) {
        // early mask word loads (latency hidden under QK MMAs)
        const uint64_t w0 = mrow0[kt];
        const uint64_t w1 = mrow1[kt];

        if (kt + 2 < 32) { stageKV((cur + 2) % 3, kt + 2); CP_COMMIT(); CP_WAIT2(); }
        else if (kt + 1 < 32) { CP_WAIT1(); }
        else { CP_WAIT0(); }
        __syncthreads();

        const uint32_t KhB = sb + cur * ASTAGE + kvoff;
        const uint32_t KlB = KhB + ATILE;
        const uint32_t VhB = KhB + 2 * ATILE;
        const uint32_t VlB = KhB + 3 * ATILE;

        // ---- scores: S = Q K^T (3-pass) ----
        float sacc[8][4];
#pragma unroll
        for (int nb = 0; nb < 8; nb++)
#pragma unroll
            for (int r = 0; r < 4; r++) sacc[nb][r] = 0.f;

#pragma unroll
        for (int ks = 0; ks < 4; ks++) {
            uint32_t kh2[8][2], kl2[8][2];
#pragma unroll
            for (int np = 0; np < 4; np++) {
                const uint32_t o = (uint32_t)(np * 16 * ATSTR) * 2 + ks * 32;
                LDSM4(kh2[2 * np][0], kh2[2 * np][1], kh2[2 * np + 1][0], kh2[2 * np + 1][1],
                      KhB + o);
                LDSM4(kl2[2 * np][0], kl2[2 * np][1], kl2[2 * np + 1][0], kl2[2 * np + 1][1],
                      KlB + o);
            }
#pragma unroll
            for (int nb = 0; nb < 8; nb++) mma16816(sacc[nb], qh[ks], kh2[nb]);
#pragma unroll
            for (int nb = 0; nb < 8; nb++) mma16816(sacc[nb], qh[ks], kl2[nb]);
#pragma unroll
            for (int nb = 0; nb < 8; nb++) mma16816(sacc[nb], ql[ks], kh2[nb]);
        }

        // ---- mask via packed bits ----
#pragma unroll
        for (int nb = 0; nb < 8; nb++) {
            const int j = nb * 8 + c4;
            if (!((w0 >> j) & 1))       sacc[nb][0] = -1e30f;
            if (!((w0 >> (j + 1)) & 1)) sacc[nb][1] = -1e30f;
            if (!((w1 >> j) & 1))       sacc[nb][2] = -1e30f;
            if (!((w1 >> (j + 1)) & 1)) sacc[nb][3] = -1e30f;
        }

        // ---- online softmax ----
        float mx0 = -1e30f, mx1 = -1e30f;
#pragma unroll
        for (int nb = 0; nb < 8; nb++) {
            mx0 = fmaxf(mx0, fmaxf(sacc[nb][0], sacc[nb][1]));
            mx1 = fmaxf(mx1, fmaxf(sacc[nb][2], sacc[nb][3]));
        }
        mx0 = fmaxf(mx0, __shfl_xor_sync(0xffffffffu, mx0, 1));
        mx0 = fmaxf(mx0, __shfl_xor_sync(0xffffffffu, mx0, 2));
        mx1 = fmaxf(mx1, __shfl_xor_sync(0xffffffffu, mx1, 1));
        mx1 = fmaxf(mx1, __shfl_xor_sync(0xffffffffu, mx1, 2));

        const float mn0 = fmaxf(mrun0, mx0);
        const float mn1 = fmaxf(mrun1, mx1);
        const float scl0 = __expf(mrun0 - mn0);
        const float scl1 = __expf(mrun1 - mn1);
        mrun0 = mn0; mrun1 = mn1;

        float rs0 = 0.f, rs1 = 0.f;
#pragma unroll
        for (int nb = 0; nb < 8; nb++) {
            sacc[nb][0] = __expf(sacc[nb][0] - mn0);
            sacc[nb][1] = __expf(sacc[nb][1] - mn0);
            sacc[nb][2] = __expf(sacc[nb][2] - mn1);
            sacc[nb][3] = __expf(sacc[nb][3] - mn1);
            rs0 += sacc[nb][0] + sacc[nb][1];
            rs1 += sacc[nb][2] + sacc[nb][3];
        }
        rs0 += __shfl_xor_sync(0xffffffffu, rs0, 1);
        rs0 += __shfl_xor_sync(0xffffffffu, rs0, 2);
        rs1 += __shfl_xor_sync(0xffffffffu, rs1, 1);
        rs1 += __shfl_xor_sync(0xffffffffu, rs1, 2);
        lrun0 = lrun0 * scl0 + rs0;
        lrun1 = lrun1 * scl1 + rs1;

#pragma unroll
        for (int nb = 0; nb < 8; nb++) {
            oacc[nb][0] *= scl0; oacc[nb][1] *= scl0;
            oacc[nb][2] *= scl1; oacc[nb][3] *= scl1;
        }

        // ---- P -> hi/lo A-fragments ----
        uint32_t pah[4][4], pal[4][4];
#pragma unroll
        for (int ks = 0; ks < 4; ks++) {
            split2(sacc[2 * ks][0],     sacc[2 * ks][1],     pah[ks][0], pal[ks][0]);
            split2(sacc[2 * ks][2],     sacc[2 * ks][3],     pah[ks][1], pal[ks][1]);
            split2(sacc[2 * ks + 1][0], sacc[2 * ks + 1][1], pah[ks][2], pal[ks][2]);
            split2(sacc[2 * ks + 1][2], sacc[2 * ks + 1][3], pah[ks][3], pal[ks][3]);
        }

        // ---- O += P V (3-pass) ----
#pragma unroll
        for (int ks = 0; ks < 4; ks++) {
            uint32_t vh2[8][2], vl2[8][2];
#pragma unroll
            for (int np = 0; np < 4; np++) {
                const uint32_t o = (uint32_t)(np * 16 * ATSTR) * 2 + ks * 32;
                LDSM4(vh2[2 * np][0], vh2[2 * np][1], vh2[2 * np + 1][0], vh2[2 * np + 1][1],
                      VhB + o);
                LDSM4(vl2[2 * np][0], vl2[2 * np][1], vl2[2 * np + 1][0], vl2[2 * np + 1][1],
                      VlB + o);
            }
#pragma unroll
            for (int nb = 0; nb < 8; nb++) mma16816(oacc[nb], pah[ks], vh2[nb]);
#pragma unroll
            for (int nb = 0; nb < 8; nb++) mma16816(oacc[nb], pah[ks], vl2[nb]);
#pragma unroll
            for (int nb = 0; nb < 8; nb++) mma16816(oacc[nb], pal[ks], vh2[nb]);
        }
        __syncthreads();

        cur = (cur + 1) % 3;
    }

    // ---- epilogue: normalize, emit hi/lo bf16 [b*s][h*dk] ----
    const float inv0 = (lrun0 > 0.f) ? 1.f / lrun0 : 0.f;
    const float inv1 = (lrun1 > 0.f) ? 1.f / lrun1 : 0.f;
    const size_t m0 = (size_t)b * SEQ + ro0;
#pragma unroll
    for (int nb = 0; nb < 8; nb++) {
        const int col = h * DK + nb * 8 + c4;
        uint32_t hi, lo;
        split2(oacc[nb][0] * inv0, oacc[nb][1] * inv0, hi, lo);
        *(uint32_t*)&Ohi[m0 * DM + col] = hi;
        *(uint32_t*)&Olo[m0 * DM + col] = lo;
        split2(oacc[nb][2] * inv1, oacc[nb][3] * inv1, hi, lo);
        *(uint32_t*)&Ohi[(m0 + 8) * DM + col] = hi;
        *(uint32_t*)&Olo[(m0 + 8) * DM + col] = lo;
    }
}

// ---------------- launch ----------------
extern "C" void kernel_launch(void* const* d_in, const int* in_sizes, int n_in,
                              void* d_out, int out_size)
{
    const float* q    = (const float*)d_in[0];
    const float* k    = (const float*)d_in[1];
    const float* v    = (const float*)d_in[2];
    const int*   mask = (const int*)  d_in[3];
    const float* wq   = (const float*)d_in[4];
    const float* bq   = (const float*)d_in[5];
    const float* wk   = (const float*)d_in[6];
    const float* wv   = (const float*)d_in[7];
    const float* bv   = (const float*)d_in[8];
    const float* wf   = (const float*)d_in[9];
    const float* bf   = (const float*)d_in[10];
    float* out = (float*)d_out;

    __nv_bfloat16 *Xhi, *Xlo, *WhT, *WlT, *Qhi, *Qlo, *Khi, *Klo, *Vhi, *Vlo;
    uint64_t* Mpk;
    cudaGetSymbolAddress((void**)&Xhi, g_Xhi);
    cudaGetSymbolAddress((void**)&Xlo, g_Xlo);
    cudaGetSymbolAddress((void**)&WhT, g_WhT);
    cudaGetSymbolAddress((void**)&WlT, g_WlT);
    cudaGetSymbolAddress((void**)&Qhi, g_Qhi);
    cudaGetSymbolAddress((void**)&Qlo, g_Qlo);
    cudaGetSymbolAddress((void**)&Khi, g_Khi);
    cudaGetSymbolAddress((void**)&Klo, g_Klo);
    cudaGetSymbolAddress((void**)&Vhi, g_Vhi);
    cudaGetSymbolAddress((void**)&Vlo, g_Vlo);
    cudaGetSymbolAddress((void**)&Mpk, g_Mpk);

    cudaFuncSetAttribute(tc_gemm,
                         cudaFuncAttributeMaxDynamicSharedMemorySize, SMEM_GEMM);
    cudaFuncSetAttribute(attn_tc,
                         cudaFuncAttributeMaxDynamicSharedMemorySize, SMEM_ATT);

    dim3 wgrid(32, 32);
    dim3 wblk(32, 8);
    conv_w<<<wgrid, wblk>>>(wq, WhT + 0 * DM * DM, WlT + 0 * DM * DM);
    conv_w<<<wgrid, wblk>>>(wk, WhT + 1 * DM * DM, WlT + 1 * DM * DM);
    conv_w<<<wgrid, wblk>>>(wv, WhT + 2 * DM * DM, WlT + 2 * DM * DM);
    conv_w<<<wgrid, wblk>>>(wf, WhT + 3 * DM * DM, WlT + 3 * DM * DM);
    pack_mask<<<(BATCH * SEQ * (SEQ / 64)) / 256, 256>>>(mask, Mpk);

    dim3 ggrid(DM / 128, MTOT / 128);   // (8, 32)

    conv_act<<<MTOT * DM / 1024, 256>>>(q, Xhi, Xlo);
    tc_gemm<<<ggrid, 256, SMEM_GEMM>>>(Xhi, Xlo, WhT + 0 * DM * DM, WlT + 0 * DM * DM,
                                       bq, nullptr, Qhi, Qlo, 1);

    conv_act<<<MTOT * DM / 1024, 256>>>(k, Xhi, Xlo);
    tc_gemm<<<ggrid, 256, SMEM_GEMM>>>(Xhi, Xlo, WhT + 1 * DM * DM, WlT + 1 * DM * DM,
                                       nullptr, nullptr, Khi, Klo, 2);

    conv_act<<<MTOT * DM / 1024, 256>>>(v, Xhi, Xlo);
    tc_gemm<<<ggrid, 256, SMEM_GEMM>>>(Xhi, Xlo, WhT + 2 * DM * DM, WlT + 2 * DM * DM,
                                       bv, nullptr, Vhi, Vlo, 3);

    attn_tc<<<dim3(SEQ / 128, BATCH * NH), 256, SMEM_ATT>>>(Qhi, Qlo, Khi, Klo,
                                                            Vhi, Vlo, Mpk, Xhi, Xlo);

    tc_gemm<<<ggrid, 256, SMEM_GEMM>>>(Xhi, Xlo, WhT + 3 * DM * DM, WlT + 3 * DM * DM,
                                       bf, out, nullptr, nullptr, 0);
}

// round 15
// speedup vs baseline: 3.1520x; 1.0476x over previous
#include <cuda_runtime.h>
#include <cuda_bf16.h>
#include <math.h>
#include <stdint.h>

// Problem constants
#define BATCH 2
#define SEQ   2048
#define DM    1024
#define NH    16
#define DK    64
#define MTOT  (BATCH*SEQ)       // 4096

// ---------------- scratch (no allocations allowed) ----------------
__device__ __nv_bfloat16 g_Ahi[3][MTOT*DM];   // activations hi (q,k,v; [0] reused by attn out)
__device__ __nv_bfloat16 g_Alo[3][MTOT*DM];
__device__ __nv_bfloat16 g_WhT[4][DM*DM];
__device__ __nv_bfloat16 g_WlT[4][DM*DM];
__device__ __nv_bfloat16 g_Qhi[MTOT*DM];
__device__ __nv_bfloat16 g_Qlo[MTOT*DM];
__device__ __nv_bfloat16 g_Khi[MTOT*DM];
__device__ __nv_bfloat16 g_Klo[MTOT*DM];
__device__ __nv_bfloat16 g_Vhi[MTOT*DM];
__device__ __nv_bfloat16 g_Vlo[MTOT*DM];
__device__ uint64_t      g_Mpk[BATCH*SEQ*(SEQ/64)];   // bit-packed mask, 1MB

__device__ __forceinline__ uint32_t smem_u32(const void* p) {
    uint32_t a;
    asm("{ .reg .u64 t; cvta.to.shared.u64 t, %1; cvt.u32.u64 %0, t; }"
        : "=r"(a) : "l"(p));
    return a;
}

#define CP16(dst_u32, src_ptr) \
    asm volatile("cp.async.ca.shared.global [%0], [%1], 16;" \
                 :: "r"(dst_u32), "l"((uint64_t)__cvta_generic_to_global(src_ptr)) : "memory")
#define CP_COMMIT() asm volatile("cp.async.commit_group;" ::: "memory")
#define CP_WAIT1()  asm volatile("cp.async.wait_group 1;" ::: "memory")
#define CP_WAIT0()  asm volatile("cp.async.wait_group 0;" ::: "memory")

#define LDSM4(r0, r1, r2, r3, addr) \
    asm volatile("ldmatrix.sync.aligned.m8n8.x4.shared.b16 {%0,%1,%2,%3}, [%4];" \
                 : "=r"(r0), "=r"(r1), "=r"(r2), "=r"(r3) : "r"(addr))

__device__ __forceinline__ void split2(float a, float b, uint32_t& hi, uint32_t& lo) {
    __nv_bfloat162 h = __float22bfloat162_rn(make_float2(a, b));
    float2 hf = __bfloat1622float2(h);
    __nv_bfloat162 l = __float22bfloat162_rn(make_float2(a - hf.x, b - hf.y));
    hi = *(uint32_t*)&h;
    lo = *(uint32_t*)&l;
}

__device__ __forceinline__ void mma16816(float* c, const uint32_t* a, const uint32_t* b) {
    asm volatile(
        "mma.sync.aligned.m16n8k16.row.col.f32.bf16.bf16.f32 "
        "{%0,%1,%2,%3},{%4,%5,%6,%7},{%8,%9},{%0,%1,%2,%3};"
        : "+f"(c[0]), "+f"(c[1]), "+f"(c[2]), "+f"(c[3])
        : "r"(a[0]), "r"(a[1]), "r"(a[2]), "r"(a[3]), "r"(b[0]), "r"(b[1]));
}

// ---------------- pre-passes (merged) ----------------
// z = which activation (0=q, 1=k, 2=v)
__global__ __launch_bounds__(256)
void conv_act3(const float* __restrict__ q, const float* __restrict__ k,
               const float* __restrict__ v,
               __nv_bfloat16* __restrict__ Ahi, __nv_bfloat16* __restrict__ Alo)
{
    const int z = blockIdx.z;
    const float* X = (z == 0) ? q : (z == 1) ? k : v;
    size_t idx = blockIdx.x * 256 + threadIdx.x;
    float4 x = ((const float4*)X)[idx];
    uint32_t h0, l0, h1, l1;
    split2(x.x, x.y, h0, l0);
    split2(x.z, x.w, h1, l1);
    ((uint2*)(Ahi + (size_t)z * MTOT * DM))[idx] = make_uint2(h0, h1);
    ((uint2*)(Alo + (size_t)z * MTOT * DM))[idx] = make_uint2(l0, l1);
}

__global__ __launch_bounds__(256)
void conv_w4(const float* __restrict__ w0, const float* __restrict__ w1,
             const float* __restrict__ w2, const float* __restrict__ w3,
             __nv_bfloat16* __restrict__ WhT, __nv_bfloat16* __restrict__ WlT)
{
    __shared__ float ts[32][33];
    const int z = blockIdx.z;
    const float* W = (z == 0) ? w0 : (z == 1) ? w1 : (z == 2) ? w2 : w3;
    __nv_bfloat16* Wh = WhT + (size_t)z * DM * DM;
    __nv_bfloat16* Wl = WlT + (size_t)z * DM * DM;
    const int tx = threadIdx.x, ty = threadIdx.y;   // (32, 8)
    const int kt = blockIdx.y * 32, nt = blockIdx.x * 32;
#pragma unroll
    for (int i = 0; i < 4; i++)
        ts[ty + 8 * i][tx] = W[(size_t)(kt + ty + 8 * i) * DM + nt + tx];
    __syncthreads();
#pragma unroll
    for (int i = 0; i < 4; i++) {
        int n = nt + ty + 8 * i;
        int k = kt + tx;
        float v = ts[tx][ty + 8 * i];
        __nv_bfloat16 h = __float2bfloat16(v);
        __nv_bfloat16 l = __float2bfloat16(v - __bfloat162float(h));
        Wh[(size_t)n * DM + k] = h;
        Wl[(size_t)n * DM + k] = l;
    }
}

__global__ __launch_bounds__(256)
void pack_mask(const int* __restrict__ mask, uint64_t* __restrict__ Mpk)
{
    int idx = blockIdx.x * 256 + threadIdx.x;
    const int4* src = (const int4*)mask + (size_t)idx * 16;
    uint64_t w = 0;
#pragma unroll
    for (int i = 0; i < 16; i++) {
        int4 v = src[i];
        uint64_t nib = (uint64_t)((v.x != 0) | ((v.y != 0) << 1) |
                                  ((v.z != 0) << 2) | ((v.w != 0) << 3));
        w |= nib << (i * 4);
    }
    Mpk[idx] = w;
}

// ==================== HMMA bf16 GEMM (pass-fused) ====================
#define BSTR  40
#define T2B   (128 * BSTR * 2)     // 10240 bytes per tile (128 x 32 halves)
#define STG2  (4 * T2B)            // 40960: Ahi, Alo, Bhi, Blo
#define SMEM_GEMM (2 * STG2)       // 81920

__global__ __launch_bounds__(256, 2)
void tc_gemm(const __nv_bfloat16* __restrict__ Xhi, const __nv_bfloat16* __restrict__ Xlo,
             const __nv_bfloat16* __restrict__ WhT, const __nv_bfloat16* __restrict__ WlT,
             const float* __restrict__ bias, float* __restrict__ Yf,
             __nv_bfloat16* __restrict__ Yh, __nv_bfloat16* __restrict__ Yl, int mode)
{
    extern __shared__ char sm[];
    const int tid  = threadIdx.x;
    const int wid  = tid >> 5;
    const int lane = tid & 31;
    const int wm   = wid >> 2;
    const int wn   = wid & 3;
    const int bm   = blockIdx.y * 128;
    const int bn   = blockIdx.x * 128;
    const uint32_t sb = smem_u32(sm);

    const int row  = tid >> 1;
    const int colh = (tid & 1) * 16;
    const uint32_t sd = sb + (uint32_t)(row * BSTR + colh) * 2;

    const __nv_bfloat16* Ah_src = Xhi + (size_t)(bm + row) * DM + colh;
    const __nv_bfloat16* Al_src = Xlo + (size_t)(bm + row) * DM + colh;
    const __nv_bfloat16* Bh_src = WhT + (size_t)(bn + row) * DM + colh;
    const __nv_bfloat16* Bl_src = WlT + (size_t)(bn + row) * DM + colh;

    auto stage = [&](int buf, int blk) {
        const int k0 = blk * 32;
        const uint32_t d = sd + buf * STG2;
        CP16(d,                Ah_src + k0);  CP16(d + 16,           Ah_src + k0 + 8);
        CP16(d + T2B,          Al_src + k0);  CP16(d + T2B + 16,     Al_src + k0 + 8);
        CP16(d + 2 * T2B,      Bh_src + k0);  CP16(d + 2 * T2B + 16, Bh_src + k0 + 8);
        CP16(d + 3 * T2B,      Bl_src + k0);  CP16(d + 3 * T2B + 16, Bl_src + k0 + 8);
    };

    const int aoff0 = (wm * 64 + ((lane >> 3) & 1) * 8 + (lane & 7)) * BSTR + (lane >> 4) * 8;
    const int boff0 = (wn * 32 + ((lane >> 4)) * 8 + (lane & 7)) * BSTR + ((lane >> 3) & 1) * 8;

    float acc[4][4][4];
#pragma unroll
    for (int i = 0; i < 4; i++)
#pragma unroll
        for (int j = 0; j < 4; j++)
#pragma unroll
            for (int r = 0; r < 4; r++) acc[i][j][r] = 0.f;

    stage(0, 0);
    CP_COMMIT();

    const int r4 = lane >> 2;
    const int c4 = (lane & 3) * 2;

    for (int it = 0; it < 32; it++) {
        const int cur = it & 1;
        if (it + 1 < 32) stage(cur ^ 1, it + 1);
        CP_COMMIT();
        CP_WAIT1();
        __syncthreads();

        const uint32_t AhB = sb + cur * STG2 + aoff0 * 2;
        const uint32_t AlB = AhB + T2B;
        const uint32_t BhB = sb + cur * STG2 + 2 * T2B + boff0 * 2;
        const uint32_t BlB = BhB + T2B;

#pragma unroll
        for (int ks = 0; ks < 2; ks++) {
            const uint32_t ko = (uint32_t)(ks * 16) * 2;
            uint32_t ah[4][4], al[4][4];
#pragma unroll
            for (int mt = 0; mt < 4; mt++) {
                const uint32_t mo = (uint32_t)(mt * 16 * BSTR) * 2 + ko;
                LDSM4(ah[mt][0], ah[mt][1], ah[mt][2], ah[mt][3], AhB + mo);
                LDSM4(al[mt][0], al[mt][1], al[mt][2], al[mt][3], AlB + mo);
            }
            {
                uint32_t bh[4][2];
#pragma unroll
                for (int np = 0; np < 2; np++)
                    LDSM4(bh[2 * np][0], bh[2 * np][1], bh[2 * np + 1][0], bh[2 * np + 1][1],
                          BhB + (uint32_t)(np * 16 * BSTR) * 2 + ko);
#pragma unroll
                for (int mt = 0; mt < 4; mt++)
#pragma unroll
                    for (int nt = 0; nt < 4; nt++)
                        mma16816(acc[mt][nt], ah[mt], bh[nt]);
#pragma unroll
                for (int mt = 0; mt < 4; mt++)
#pragma unroll
                    for (int nt = 0; nt < 4; nt++)
                        mma16816(acc[mt][nt], al[mt], bh[nt]);
            }
            {
                uint32_t bl[4][2];
#pragma unroll
                for (int np = 0; np < 2; np++)
                    LDSM4(bl[2 * np][0], bl[2 * np][1], bl[2 * np + 1][0], bl[2 * np + 1][1],
                          BlB + (uint32_t)(np * 16 * BSTR) * 2 + ko);
#pragma unroll
                for (int mt = 0; mt < 4; mt++)
#pragma unroll
                    for (int nt = 0; nt < 4; nt++)
                        mma16816(acc[mt][nt], ah[mt], bl[nt]);
            }
        }
        __syncthreads();
    }

    // ---------------- epilogue ----------------
#pragma unroll
    for (int mt = 0; mt < 4; mt++) {
#pragma unroll
        for (int rr = 0; rr < 2; rr++) {
            const int m  = bm + wm * 64 + mt * 16 + r4 + rr * 8;
            const int bq = m >> 11, sq = m & (SEQ - 1);
#pragma unroll
            for (int nt = 0; nt < 4; nt++) {
                const int n = bn + wn * 32 + nt * 8 + c4;
                float v0 = acc[mt][nt][rr * 2], v1 = acc[mt][nt][rr * 2 + 1];
                if (bias) { v0 += bias[n]; v1 += bias[n + 1]; }
                if (mode == 1) { v0 *= 0.125f; v1 *= 0.125f; }
                if (mode == 0) {
                    *(float2*)&Yf[(size_t)m * DM + n] = make_float2(v0, v1);
                } else if (mode == 3) {
                    const int hh = n >> 6, dk = n & 63;
                    size_t i0 = ((size_t)(bq * NH + hh) * DK + dk) * SEQ + sq;
                    __nv_bfloat16 h0 = __float2bfloat16(v0);
                    __nv_bfloat16 h1 = __float2bfloat16(v1);
                    Yh[i0]       = h0;
                    Yh[i0 + SEQ] = h1;
                    Yl[i0]       = __float2bfloat16(v0 - __bfloat162float(h0));
                    Yl[i0 + SEQ] = __float2bfloat16(v1 - __bfloat162float(h1));
                } else {
                    uint32_t hi, lo;
                    split2(v0, v1, hi, lo);
                    const int hh = n >> 6, dk = n & 63;
                    size_t idx = ((size_t)(bq * NH + hh) * SEQ + sq) * DK + dk;
                    *(uint32_t*)&Yh[idx] = hi;
                    *(uint32_t*)&Yl[idx] = lo;
                }
            }
        }
    }
}

// ==================== HMMA flash attention ====================
// grid (16, 32): Q tile 128 rows, 8 warps x 16 rows. K-tiles of 64, 32 iters.
// 2-stage cp.async KV pipeline, 2 CTAs/SM; bit-packed mask.
#define ATSTR 72
#define ATILE (64 * ATSTR * 2)    // 9216 B
#define ASTAGE (4 * ATILE)        // 36864: Khi, Klo, Vhi, Vlo
#define QTILE (128 * ATSTR * 2)   // 18432
#define SMEM_ATT (2 * ASTAGE)     // 73728

__global__ __launch_bounds__(256, 2)
void attn_tc(const __nv_bfloat16* __restrict__ Qhi_, const __nv_bfloat16* __restrict__ Qlo_,
             const __nv_bfloat16* __restrict__ Khi_, const __nv_bfloat16* __restrict__ Klo_,
             const __nv_bfloat16* __restrict__ Vhi_, const __nv_bfloat16* __restrict__ Vlo_,
             const uint64_t* __restrict__ Mpk,
             __nv_bfloat16* __restrict__ Ohi, __nv_bfloat16* __restrict__ Olo)
{
    extern __shared__ char sm[];
    const int tid  = threadIdx.x;
    const int wid  = tid >> 5;
    const int lane = tid & 31;
    const int r4   = lane >> 2;
    const int c4   = (lane & 3) * 2;
    const int qt   = blockIdx.x;
    const int bh   = blockIdx.y;
    const int b    = bh >> 4;
    const int h    = bh & 15;
    const uint32_t sb = smem_u32(sm);

    // ---- stage Q hi/lo (128x64) into the 2-stage area, extract frags ----
#pragma unroll
    for (int i = 0; i < 4; i++) {
        int c    = tid + i * 256;
        int qrow = c >> 3;
        int off  = (c & 7) * 8;
        const __nv_bfloat16* s0 = Qhi_ + ((size_t)bh * SEQ + qt * 128 + qrow) * DK + off;
        const __nv_bfloat16* s1 = Qlo_ + ((size_t)bh * SEQ + qt * 128 + qrow) * DK + off;
        uint32_t d = sb + (uint32_t)(qrow * ATSTR + off) * 2;
        CP16(d, s0);
        CP16(d + QTILE, s1);
    }
    CP_COMMIT();
    CP_WAIT0();
    __syncthreads();

    uint32_t qh[4][4], ql[4][4];
    {
        const uint32_t qoff = (uint32_t)((wid * 16 + ((lane >> 3) & 1) * 8 + (lane & 7)) * ATSTR
                                          + (lane >> 4) * 8) * 2;
#pragma unroll
        for (int ks = 0; ks < 4; ks++) {
            LDSM4(qh[ks][0], qh[ks][1], qh[ks][2], qh[ks][3], sb + qoff + ks * 32);
            LDSM4(ql[ks][0], ql[ks][1], ql[ks][2], ql[ks][3], sb + QTILE + qoff + ks * 32);
        }
    }
    __syncthreads();   // Q area reused for KV staging

    auto stageKV = [&](int buf, int kt) {
        const int krow = tid >> 2;             // 0..63
        const int off  = (tid & 3) * 16;       // halves
        uint32_t d = sb + buf * ASTAGE + (uint32_t)(krow * ATSTR + off) * 2;
        const __nv_bfloat16* k0 = Khi_ + ((size_t)bh * SEQ + kt * 64 + krow) * DK + off;
        const __nv_bfloat16* k1 = Klo_ + ((size_t)bh * SEQ + kt * 64 + krow) * DK + off;
        const __nv_bfloat16* v0 = Vhi_ + ((size_t)bh * DK + krow) * SEQ + kt * 64 + off;
        const __nv_bfloat16* v1 = Vlo_ + ((size_t)bh * DK + krow) * SEQ + kt * 64 + off;
        CP16(d,                  k0);     CP16(d + 16,              k0 + 8);
        CP16(d + ATILE,          k1);     CP16(d + ATILE + 16,      k1 + 8);
        CP16(d + 2 * ATILE,      v0);     CP16(d + 2 * ATILE + 16,  v0 + 8);
        CP16(d + 3 * ATILE,      v1);     CP16(d + 3 * ATILE + 16,  v1 + 8);
    };

    stageKV(0, 0);
    CP_COMMIT();

    float oacc[8][4];
#pragma unroll
    for (int nb = 0; nb < 8; nb++)
#pragma unroll
        for (int r = 0; r < 4; r++) oacc[nb][r] = 0.f;
    float mrun0 = -1e30f, mrun1 = -1e30f, lrun0 = 0.f, lrun1 = 0.f;

    const int ro0 = qt * 128 + wid * 16 + r4;
    const uint64_t* mrow0 = Mpk + ((size_t)b * SEQ + ro0) * (SEQ / 64);
    const uint64_t* mrow1 = mrow0 + 8 * (SEQ / 64);

    const uint32_t kvoff = (uint32_t)(((lane >> 4) * 8 + (lane & 7)) * ATSTR
                                       + ((lane >> 3) & 1) * 8) * 2;

    for (int kt = 0; kt < 32; kt++) {
        const int cur = kt & 1;
        const uint64_t w0 = mrow0[kt];
        const uint64_t w1 = mrow1[kt];

        if (kt + 1 < 32) { stageKV(cur ^ 1, kt + 1); CP_COMMIT(); CP_WAIT1(); }
        else             { CP_WAIT0(); }
        __syncthreads();

        const uint32_t KhB = sb + cur * ASTAGE + kvoff;
        const uint32_t KlB = KhB + ATILE;
        const uint32_t VhB = KhB + 2 * ATILE;
        const uint32_t VlB = KhB + 3 * ATILE;

        // ---- scores: S = Q K^T (3 passes, register-staggered) ----
        float sacc[8][4];
#pragma unroll
        for (int nb = 0; nb < 8; nb++)
#pragma unroll
            for (int r = 0; r < 4; r++) sacc[nb][r] = 0.f;

#pragma unroll
        for (int ks = 0; ks < 4; ks++) {
            {
                uint32_t kh2[8][2];
#pragma unroll
                for (int np = 0; np < 4; np++) {
                    const uint32_t o = (uint32_t)(np * 16 * ATSTR) * 2 + ks * 32;
                    LDSM4(kh2[2 * np][0], kh2[2 * np][1], kh2[2 * np + 1][0],
                          kh2[2 * np + 1][1], KhB + o);
                }
#pragma unroll
                for (int nb = 0; nb < 8; nb++) mma16816(sacc[nb], qh[ks], kh2[nb]);
#pragma unroll
                for (int nb = 0; nb < 8; nb++) mma16816(sacc[nb], ql[ks], kh2[nb]);
            }
            {
                uint32_t kl2[8][2];
#pragma unroll
                for (int np = 0; np < 4; np++) {
                    const uint32_t o = (uint32_t)(np * 16 * ATSTR) * 2 + ks * 32;
                    LDSM4(kl2[2 * np][0], kl2[2 * np][1], kl2[2 * np + 1][0],
                          kl2[2 * np + 1][1], KlB + o);
                }
#pragma unroll
                for (int nb = 0; nb < 8; nb++) mma16816(sacc[nb], qh[ks], kl2[nb]);
            }
        }

        // ---- mask via packed bits ----
#pragma unroll
        for (int nb = 0; nb < 8; nb++) {
            const int j = nb * 8 + c4;
            if (!((w0 >> j) & 1))       sacc[nb][0] = -1e30f;
            if (!((w0 >> (j + 1)) & 1)) sacc[nb][1] = -1e30f;
            if (!((w1 >> j) & 1))       sacc[nb][2] = -1e30f;
            if (!((w1 >> (j + 1)) & 1)) sacc[nb][3] = -1e30f;
        }

        // ---- online softmax ----
        float mx0 = -1e30f, mx1 = -1e30f;
#pragma unroll
        for (int nb = 0; nb < 8; nb++) {
            mx0 = fmaxf(mx0, fmaxf(sacc[nb][0], sacc[nb][1]));
            mx1 = fmaxf(mx1, fmaxf(sacc[nb][2], sacc[nb][3]));
        }
        mx0 = fmaxf(mx0, __shfl_xor_sync(0xffffffffu, mx0, 1));
        mx0 = fmaxf(mx0, __shfl_xor_sync(0xffffffffu, mx0, 2));
        mx1 = fmaxf(mx1, __shfl_xor_sync(0xffffffffu, mx1, 1));
        mx1 = fmaxf(mx1, __shfl_xor_sync(0xffffffffu, mx1, 2));

        const float mn0 = fmaxf(mrun0, mx0);
        const float mn1 = fmaxf(mrun1, mx1);
        const float scl0 = __expf(mrun0 - mn0);
        const float scl1 = __expf(mrun1 - mn1);
        mrun0 = mn0; mrun1 = mn1;

        float rs0 = 0.f, rs1 = 0.f;
#pragma unroll
        for (int nb = 0; nb < 8; nb++) {
            sacc[nb][0] = __expf(sacc[nb][0] - mn0);
            sacc[nb][1] = __expf(sacc[nb][1] - mn0);
            sacc[nb][2] = __expf(sacc[nb][2] - mn1);
            sacc[nb][3] = __expf(sacc[nb][3] - mn1);
            rs0 += sacc[nb][0] + sacc[nb][1];
            rs1 += sacc[nb][2] + sacc[nb][3];
        }
        rs0 += __shfl_xor_sync(0xffffffffu, rs0, 1);
        rs0 += __shfl_xor_sync(0xffffffffu, rs0, 2);
        rs1 += __shfl_xor_sync(0xffffffffu, rs1, 1);
        rs1 += __shfl_xor_sync(0xffffffffu, rs1, 2);
        lrun0 = lrun0 * scl0 + rs0;
        lrun1 = lrun1 * scl1 + rs1;

#pragma unroll
        for (int nb = 0; nb < 8; nb++) {
            oacc[nb][0] *= scl0; oacc[nb][1] *= scl0;
            oacc[nb][2] *= scl1; oacc[nb][3] *= scl1;
        }

        // ---- P -> hi/lo A-fragments (overwrite-friendly: after this sacc dead) ----
        uint32_t pah[4][4], pal[4][4];
#pragma unroll
        for (int ks = 0; ks < 4; ks++) {
            split2(sacc[2 * ks][0],     sacc[2 * ks][1],     pah[ks][0], pal[ks][0]);
            split2(sacc[2 * ks][2],     sacc[2 * ks][3],     pah[ks][1], pal[ks][1]);
            split2(sacc[2 * ks + 1][0], sacc[2 * ks + 1][1], pah[ks][2], pal[ks][2]);
            split2(sacc[2 * ks + 1][2], sacc[2 * ks + 1][3], pah[ks][3], pal[ks][3]);
        }

        // ---- O += P V (3 passes, register-staggered) ----
#pragma unroll
        for (int ks = 0; ks < 4; ks++) {
            {
                uint32_t vh2[8][2];
#pragma unroll
                for (int np = 0; np < 4; np++) {
                    const uint32_t o = (uint32_t)(np * 16 * ATSTR) * 2 + ks * 32;
                    LDSM4(vh2[2 * np][0], vh2[2 * np][1], vh2[2 * np + 1][0],
                          vh2[2 * np + 1][1], VhB + o);
                }
#pragma unroll
                for (int nb = 0; nb < 8; nb++) mma16816(oacc[nb], pah[ks], vh2[nb]);
#pragma unroll
                for (int nb = 0; nb < 8; nb++) mma16816(oacc[nb], pal[ks], vh2[nb]);
            }
            {
                uint32_t vl2[8][2];
#pragma unroll
                for (int np = 0; np < 4; np++) {
                    const uint32_t o = (uint32_t)(np * 16 * ATSTR) * 2 + ks * 32;
                    LDSM4(vl2[2 * np][0], vl2[2 * np][1], vl2[2 * np + 1][0],
                          vl2[2 * np + 1][1], VlB + o);
                }
#pragma unroll
                for (int nb = 0; nb < 8; nb++) mma16816(oacc[nb], pah[ks], vl2[nb]);
            }
        }
        __syncthreads();
    }

    // ---- epilogue: normalize, emit hi/lo bf16 [b*s][h*dk] ----
    const float inv0 = (lrun0 > 0.f) ? 1.f / lrun0 : 0.f;
    const float inv1 = (lrun1 > 0.f) ? 1.f / lrun1 : 0.f;
    const size_t m0 = (size_t)b * SEQ + ro0;
#pragma unroll
    for (int nb = 0; nb < 8; nb++) {
        const int col = h * DK + nb * 8 + c4;
        uint32_t hi, lo;
        split2(oacc[nb][0] * inv0, oacc[nb][1] * inv0, hi, lo);
        *(uint32_t*)&Ohi[m0 * DM + col] = hi;
        *(uint32_t*)&Olo[m0 * DM + col] = lo;
        split2(oacc[nb][2] * inv1, oacc[nb][3] * inv1, hi, lo);
        *(uint32_t*)&Ohi[(m0 + 8) * DM + col] = hi;
        *(uint32_t*)&Olo[(m0 + 8) * DM + col] = lo;
    }
}

// ---------------- launch ----------------
extern "C" void kernel_launch(void* const* d_in, const int* in_sizes, int n_in,
                              void* d_out, int out_size)
{
    const float* q    = (const float*)d_in[0];
    const float* k    = (const float*)d_in[1];
    const float* v    = (const float*)d_in[2];
    const int*   mask = (const int*)  d_in[3];
    const float* wq   = (const float*)d_in[4];
    const float* bq   = (const float*)d_in[5];
    const float* wk   = (const float*)d_in[6];
    const float* wv   = (const float*)d_in[7];
    const float* bv   = (const float*)d_in[8];
    const float* wf   = (const float*)d_in[9];
    const float* bf   = (const float*)d_in[10];
    float* out = (float*)d_out;

    __nv_bfloat16 *Ahi, *Alo, *WhT, *WlT, *Qhi, *Qlo, *Khi, *Klo, *Vhi, *Vlo;
    uint64_t* Mpk;
    cudaGetSymbolAddress((void**)&Ahi, g_Ahi);
    cudaGetSymbolAddress((void**)&Alo, g_Alo);
    cudaGetSymbolAddress((void**)&WhT, g_WhT);
    cudaGetSymbolAddress((void**)&WlT, g_WlT);
    cudaGetSymbolAddress((void**)&Qhi, g_Qhi);
    cudaGetSymbolAddress((void**)&Qlo, g_Qlo);
    cudaGetSymbolAddress((void**)&Khi, g_Khi);
    cudaGetSymbolAddress((void**)&Klo, g_Klo);
    cudaGetSymbolAddress((void**)&Vhi, g_Vhi);
    cudaGetSymbolAddress((void**)&Vlo, g_Vlo);
    cudaGetSymbolAddress((void**)&Mpk, g_Mpk);

    cudaFuncSetAttribute(tc_gemm,
                         cudaFuncAttributeMaxDynamicSharedMemorySize, SMEM_GEMM);
    cudaFuncSetAttribute(attn_tc,
                         cudaFuncAttributeMaxDynamicSharedMemorySize, SMEM_ATT);

    // merged pre-passes
    pack_mask<<<(BATCH * SEQ * (SEQ / 64)) / 256, 256>>>(mask, Mpk);
    conv_w4<<<dim3(32, 32, 4), dim3(32, 8)>>>(wq, wk, wv, wf, WhT, WlT);
    conv_act3<<<dim3(MTOT * DM / 1024, 1, 3), 256>>>(q, k, v, Ahi, Alo);

    dim3 ggrid(DM / 128, MTOT / 128);   // (8, 32)

    tc_gemm<<<ggrid, 256, SMEM_GEMM>>>(Ahi + 0 * (size_t)MTOT * DM, Alo + 0 * (size_t)MTOT * DM,
                                       WhT + 0 * DM * DM, WlT + 0 * DM * DM,
                                       bq, nullptr, Qhi, Qlo, 1);
    tc_gemm<<<ggrid, 256, SMEM_GEMM>>>(Ahi + 1 * (size_t)MTOT * DM, Alo + 1 * (size_t)MTOT * DM,
                                       WhT + 1 * DM * DM, WlT + 1 * DM * DM,
                                       nullptr, nullptr, Khi, Klo, 2);
    tc_gemm<<<ggrid, 256, SMEM_GEMM>>>(Ahi + 2 * (size_t)MTOT * DM, Alo + 2 * (size_t)MTOT * DM,
                                       WhT + 2 * DM * DM, WlT + 2 * DM * DM,
                                       bv, nullptr, Vhi, Vlo, 3);

    // attention writes hi/lo bf16 directly into activation slot 0 (final GEMM input)
    attn_tc<<<dim3(SEQ / 128, BATCH * NH), 256, SMEM_ATT>>>(Qhi, Qlo, Khi, Klo,
                                                            Vhi, Vlo, Mpk, Ahi, Alo);

    tc_gemm<<<ggrid, 256, SMEM_GEMM>>>(Ahi, Alo,
                                       WhT + 3 * DM * DM, WlT + 3 * DM * DM,
                                       bf, out, nullptr, nullptr, 0);
}